// round 11
// baseline (speedup 1.0000x reference)
#include <cuda_runtime.h>
#include <cuda_fp16.h>
#include <cstdint>
#include <math.h>

#define BATCH 2
#define SEQ   4096
#define DMODEL 1024
#define NHEAD 4
#define DK    256
#define MS (BATCH * SEQ)
#define SCALE_F (1.0f / 16.0f)
#define DQK (DMODEL + DK)          // 1280: merged Q|K projection width

#define BM 128
#define BN 128
#define TILE_B 16384

// O-proj (2-phase): 3 tiles/stage, 2 stages -> 96KB, 2 CTA/SM
#define P_STAGES 2
#define STAGE3_B (3 * TILE_B)
#define G2_SMEM (P_STAGES * STAGE3_B)

// 1-phase GEMMs: 2 tiles/stage, 3 stages -> 96KB, 2 CTA/SM
#define STAGES 3
#define STAGE2_B (2 * TILE_B)
#define G1_SMEM (STAGES * STAGE2_B)

// fused attention tiles
#define QB 64                      // q rows per CTA
#define KBLK 64                    // keys per iteration
// smem offsets (bytes): Q 32K | K 32K | V 32K | P 8K | rowsum 256
#define AT_Q 0
#define AT_K 32768
#define AT_V 65536
#define AT_P 98304
#define AT_RS 106496
#define AT_SMEM 106752

// ---------------------------------------------------------------------------
// Device scratch
// ---------------------------------------------------------------------------
__device__ __align__(256) __half g_Xf[(size_t)MS * DMODEL];
__device__ __align__(256) __half g_Wqk[(size_t)DQK * DMODEL];
__device__ __align__(256) __half g_Wv[(size_t)DK * DMODEL];
__device__ __align__(256) __half g_Woh[(size_t)DMODEL * DMODEL];
__device__ __align__(256) __half g_Wol[(size_t)DMODEL * DMODEL];
__device__ __align__(256) __half g_QK[(size_t)MS * DQK];
__device__ __align__(256) __half g_Vt[(size_t)BATCH * DK * SEQ];
__device__ __align__(256) __half g_M[(size_t)MS * DMODEL];

// ---------------------------------------------------------------------------
// PTX helpers
// ---------------------------------------------------------------------------
__device__ __forceinline__ uint32_t smem_u32(const void* p) {
    uint32_t a;
    asm("{ .reg .u64 t; cvta.to.shared.u64 t, %1; cvt.u32.u64 %0, t; }"
        : "=r"(a) : "l"(p));
    return a;
}
__device__ __forceinline__ void cp16(uint32_t s, const void* g) {
    asm volatile("cp.async.cg.shared.global [%0], [%1], 16;" :: "r"(s), "l"(g));
}
#define CP_COMMIT() asm volatile("cp.async.commit_group;" ::: "memory")
#define CP_WAIT0()  asm volatile("cp.async.wait_group 0;" ::: "memory")
#define CP_WAIT1()  asm volatile("cp.async.wait_group 1;" ::: "memory")
#define CP_WAIT2()  asm volatile("cp.async.wait_group 2;" ::: "memory")

__device__ __forceinline__ void ldsm4(uint32_t* r, uint32_t addr) {
    asm volatile("ldmatrix.sync.aligned.m8n8.x4.shared.b16 {%0,%1,%2,%3}, [%4];"
                 : "=r"(r[0]), "=r"(r[1]), "=r"(r[2]), "=r"(r[3]) : "r"(addr));
}
__device__ __forceinline__ void mma_f16(float* c, const uint32_t* a,
                                        uint32_t b0, uint32_t b1) {
    asm volatile(
        "mma.sync.aligned.m16n8k16.row.col.f32.f16.f16.f32 "
        "{%0,%1,%2,%3}, {%4,%5,%6,%7}, {%8,%9}, {%0,%1,%2,%3};\n"
        : "+f"(c[0]), "+f"(c[1]), "+f"(c[2]), "+f"(c[3])
        : "r"(a[0]), "r"(a[1]), "r"(a[2]), "r"(a[3]), "r"(b0), "r"(b1));
}
__device__ __forceinline__ uint32_t frag_addr(uint32_t tbase, int rowBase,
                                              int ks, int lane) {
    int row = rowBase + (lane & 15);
    int chunk = ks * 2 + (lane >> 4);
    int sw = chunk ^ (row & 7);
    return tbase + row * 128 + sw * 16;
}

// ---------------------------------------------------------------------------
// Fused attention: per (b,h), Q-block of 64 rows.
// S tile = exp(SCALE * Q Kblk^T) computed in registers, bounced via smem as
// fp16 P, PV accumulated in registers across all key blocks; rowsums in smem.
// ---------------------------------------------------------------------------
__global__ void __launch_bounds__(256, 2)
attn_fused(const __half* __restrict__ QKbuf, const __half* __restrict__ Vt,
           __half* __restrict__ M)
{
    extern __shared__ char smem[];
    const uint32_t sbase = smem_u32(smem);
    const uint32_t sQ = sbase + AT_Q;
    const uint32_t sK = sbase + AT_K;
    const uint32_t sV = sbase + AT_V;
    const uint32_t sP = sbase + AT_P;
    float* rowsum = (float*)(smem + AT_RS);
    char* pBase = smem + AT_P;

    const int tid = threadIdx.x;
    const int wid = tid >> 5;
    const int lid = tid & 31;
    const int g = lid >> 2;
    const int tq = lid & 3;

    const int zbh = blockIdx.x;           // b*NHEAD + h
    const int zb = zbh >> 2;
    const int zh = zbh & 3;
    const int qBase = blockIdx.y * QB;

    const __half* Qg = QKbuf + (long long)zb * SEQ * DQK
                       + (long long)qBase * DQK + zh * DK;
    const __half* Kg = QKbuf + (long long)zb * SEQ * DQK + DMODEL;
    const __half* Vg = Vt + (long long)zb * DK * SEQ;

    if (tid < QB) rowsum[tid] = 0.0f;

    // load Q (64 rows x 256 d = 4 chunks of 64r x 128B)
#pragma unroll
    for (int j = 0; j < 8; j++) {
        int idx = tid + j * 256;          // 0..2047 (16B units)
        int chunk = idx >> 9;
        int rem = idx & 511;
        int row = rem >> 3;
        int c = rem & 7;
        int sw = c ^ (row & 7);
        cp16(sQ + chunk * 8192 + row * 128 + sw * 16,
             Qg + (long long)row * DQK + chunk * 64 + c * 8);
    }
    CP_COMMIT();

    const int warpQ = wid >> 2;           // 0..1 (32-q half)
    const int warpX = wid & 3;            // 0..3 (key group / d group)

    float out[2][8][4];
#pragma unroll
    for (int mt = 0; mt < 2; mt++)
#pragma unroll
        for (int n8 = 0; n8 < 8; n8++)
#pragma unroll
            for (int v = 0; v < 4; v++) out[mt][n8][v] = 0.0f;

    for (int kb = 0; kb < SEQ / KBLK; kb++) {
        // ---- load K block (64 keys x 256 d) and V block (256 d x 64 keys)
        const __half* Kt = Kg + (long long)(kb * KBLK) * DQK;
#pragma unroll
        for (int j = 0; j < 8; j++) {
            int idx = tid + j * 256;
            int chunk = idx >> 9;
            int rem = idx & 511;
            int row = rem >> 3;
            int c = rem & 7;
            int sw = c ^ (row & 7);
            cp16(sK + chunk * 8192 + row * 128 + sw * 16,
                 Kt + (long long)row * DQK + chunk * 64 + c * 8);
        }
        const __half* Vtt = Vg + kb * KBLK;
#pragma unroll
        for (int j = 0; j < 8; j++) {
            int idx = tid + j * 256;      // 256 rows x 8 chunks
            int row = idx >> 3;
            int c = idx & 7;
            int sw = c ^ (row & 7);
            cp16(sV + row * 128 + sw * 16,
                 Vtt + (long long)row * SEQ + c * 8);
        }
        CP_COMMIT();
        CP_WAIT0();
        __syncthreads();

        // ---- QK: S = Q @ Kblk^T, warp tile 32q x 16keys
        float sacc[2][2][4];
#pragma unroll
        for (int mt = 0; mt < 2; mt++)
#pragma unroll
            for (int nt = 0; nt < 2; nt++)
#pragma unroll
                for (int v = 0; v < 4; v++) sacc[mt][nt][v] = 0.0f;

#pragma unroll
        for (int kc = 0; kc < 4; kc++) {
#pragma unroll
            for (int ks = 0; ks < 4; ks++) {
                uint32_t qa[2][4], kf[4];
#pragma unroll
                for (int mt = 0; mt < 2; mt++)
                    ldsm4(qa[mt], frag_addr(sQ + kc * 8192,
                                            warpQ * 32 + mt * 16, ks, lid));
                ldsm4(kf, frag_addr(sK + kc * 8192, warpX * 16, ks, lid));
#pragma unroll
                for (int mt = 0; mt < 2; mt++) {
                    mma_f16(sacc[mt][0], qa[mt], kf[0], kf[2]);
                    mma_f16(sacc[mt][1], qa[mt], kf[1], kf[3]);
                }
            }
        }

        // ---- exp + rowsum + P -> smem (fp16, swizzled tile layout)
#pragma unroll
        for (int mt = 0; mt < 2; mt++) {
            const int pr0 = warpQ * 32 + mt * 16 + g;
            const int pr1 = pr0 + 8;
            float rs0 = 0.0f, rs1 = 0.0f;
#pragma unroll
            for (int nt = 0; nt < 2; nt++) {
                float e0 = __expf(sacc[mt][nt][0] * SCALE_F);
                float e1 = __expf(sacc[mt][nt][1] * SCALE_F);
                float e2 = __expf(sacc[mt][nt][2] * SCALE_F);
                float e3 = __expf(sacc[mt][nt][3] * SCALE_F);
                rs0 += e0 + e1;
                rs1 += e2 + e3;
                const int pcol = warpX * 16 + nt * 8 + tq * 2;
                const int byte = pcol * 2;
                const int ch = byte >> 4;
                const int wi = byte & 15;
                *reinterpret_cast<__half2*>(
                    pBase + pr0 * 128 + ((ch ^ (pr0 & 7)) << 4) + wi) =
                    __floats2half2_rn(e0, e1);
                *reinterpret_cast<__half2*>(
                    pBase + pr1 * 128 + ((ch ^ (pr1 & 7)) << 4) + wi) =
                    __floats2half2_rn(e2, e3);
            }
            rs0 += __shfl_xor_sync(0xffffffffu, rs0, 1);
            rs0 += __shfl_xor_sync(0xffffffffu, rs0, 2);
            rs1 += __shfl_xor_sync(0xffffffffu, rs1, 1);
            rs1 += __shfl_xor_sync(0xffffffffu, rs1, 2);
            if (tq == 0) {
                atomicAdd(&rowsum[pr0], rs0);
                atomicAdd(&rowsum[pr1], rs1);
            }
        }
        __syncthreads();

        // ---- PV: out += P @ Vblk, warp tile 32q x 64d
#pragma unroll
        for (int ks = 0; ks < 4; ks++) {
            uint32_t pa[2][4], vb[4][4];
#pragma unroll
            for (int mt = 0; mt < 2; mt++)
                ldsm4(pa[mt], frag_addr(sP, warpQ * 32 + mt * 16, ks, lid));
#pragma unroll
            for (int ng = 0; ng < 4; ng++)
                ldsm4(vb[ng], frag_addr(sV, warpX * 64 + ng * 16, ks, lid));
#pragma unroll
            for (int mt = 0; mt < 2; mt++)
#pragma unroll
                for (int n8 = 0; n8 < 8; n8++)
                    mma_f16(out[mt][n8], pa[mt],
                            vb[n8 >> 1][n8 & 1], vb[n8 >> 1][(n8 & 1) + 2]);
        }
        __syncthreads();   // before next iteration overwrites K/V/P
    }

    // ---- epilogue: divide by rowsum, write merged-head fp16 M
#pragma unroll
    for (int mt = 0; mt < 2; mt++) {
        const int r0 = warpQ * 32 + mt * 16 + g;
        const int r1 = r0 + 8;
        const float inv0 = __frcp_rn(rowsum[r0]);
        const float inv1 = __frcp_rn(rowsum[r1]);
        const long long gr0 = (long long)zb * SEQ + qBase + r0;
        const long long gr1 = gr0 + 8;
#pragma unroll
        for (int n8 = 0; n8 < 8; n8++) {
            const int col = zh * DK + warpX * 64 + n8 * 8 + tq * 2;
            *reinterpret_cast<__half2*>(M + gr0 * DMODEL + col) =
                __floats2half2_rn(out[mt][n8][0] * inv0, out[mt][n8][1] * inv0);
            *reinterpret_cast<__half2*>(M + gr1 * DMODEL + col) =
                __floats2half2_rn(out[mt][n8][2] * inv1, out[mt][n8][3] * inv1);
        }
    }
}

// ---------------------------------------------------------------------------
// 2-phase fp16 GEMM (O-proj): C = A*B0^T + A*B1^T -> fp32.
// ---------------------------------------------------------------------------
__global__ void __launch_bounds__(256, 2)
gemm_2ph(const __half* __restrict__ A0,
         const __half* __restrict__ B0, const __half* __restrict__ B1,
         float* __restrict__ Cf,
         int K, int lda, int ldb, int ldc)
{
    extern __shared__ char smem[];
    const uint32_t sbase = smem_u32(smem);
    const int tid = threadIdx.x;
    const int wid = tid >> 5;
    const int lid = tid & 31;

    const int rowBase = blockIdx.y * BM;
    const int colBase = blockIdx.x * BN;

    const __half* A0_ = A0 + (long long)rowBase * lda;
    const __half* B0_ = B0 + (long long)colBase * ldb;
    const __half* B1_ = B1 + (long long)colBase * ldb;

    const int warpM = (wid >> 2) * 64;
    const int warpN = (wid & 3) * 32;

    float acc[4][4][4];
#pragma unroll
    for (int i = 0; i < 4; i++)
#pragma unroll
        for (int j = 0; j < 4; j++)
#pragma unroll
            for (int v = 0; v < 4; v++) acc[i][j][v] = 0.0f;

    const int nK = K >> 6;

    auto load_tile = [&](const __half* P, int ld, uint32_t tb, int k0) {
#pragma unroll
        for (int j = 0; j < 4; j++) {
            int idx = tid + j * 256;
            int row = idx >> 3;
            int c = idx & 7;
            int sw = c ^ (row & 7);
            cp16(tb + row * 128 + sw * 16, P + (long long)row * ld + k0 + c * 8);
        }
    };
    auto load_stage = [&](int t, int buf) {
        const int k0 = t << 6;
        const uint32_t sS = sbase + buf * STAGE3_B;
        load_tile(A0_, lda, sS, k0);
        load_tile(B0_, ldb, sS + TILE_B, k0);
        load_tile(B1_, ldb, sS + 2 * TILE_B, k0);
    };

#pragma unroll
    for (int s = 0; s < P_STAGES; s++) {
        if (s < nK) load_stage(s, s);
        CP_COMMIT();
    }

    for (int t = 0; t < nK; t++) {
        const int buf = t & (P_STAGES - 1);
        CP_WAIT1();
        __syncthreads();

        const uint32_t sS = sbase + buf * STAGE3_B;
        const uint32_t sA = sS;
        const uint32_t sB0 = sS + TILE_B;
        const uint32_t sB1 = sS + 2 * TILE_B;

#pragma unroll
        for (int ks = 0; ks < 4; ks++) {
            uint32_t af[4][4], bf[2][4];
#pragma unroll
            for (int i = 0; i < 4; i++)
                ldsm4(af[i], frag_addr(sA, warpM + i * 16, ks, lid));
#pragma unroll
            for (int j = 0; j < 2; j++)
                ldsm4(bf[j], frag_addr(sB0, warpN + j * 16, ks, lid));
#pragma unroll
            for (int i = 0; i < 4; i++)
#pragma unroll
                for (int j = 0; j < 4; j++)
                    mma_f16(acc[i][j], af[i],
                            bf[j >> 1][j & 1], bf[j >> 1][(j & 1) + 2]);
#pragma unroll
            for (int j = 0; j < 2; j++)
                ldsm4(bf[j], frag_addr(sB1, warpN + j * 16, ks, lid));
#pragma unroll
            for (int i = 0; i < 4; i++)
#pragma unroll
                for (int j = 0; j < 4; j++)
                    mma_f16(acc[i][j], af[i],
                            bf[j >> 1][j & 1], bf[j >> 1][(j & 1) + 2]);
        }
        __syncthreads();

        const int nt = t + P_STAGES;
        if (nt < nK) load_stage(nt, buf);
        CP_COMMIT();
    }

    const int g = lid >> 2;
    const int tq = lid & 3;
#pragma unroll
    for (int i = 0; i < 4; i++) {
        const long long r0 = rowBase + warpM + i * 16 + g;
        const long long r1 = r0 + 8;
#pragma unroll
        for (int j = 0; j < 4; j++) {
            const int col = colBase + warpN + j * 8 + tq * 2;
            *reinterpret_cast<float2*>(Cf + r0 * ldc + col) =
                make_float2(acc[i][j][0], acc[i][j][1]);
            *reinterpret_cast<float2*>(Cf + r1 * ldc + col) =
                make_float2(acc[i][j][2], acc[i][j][3]);
        }
    }
}

// ---------------------------------------------------------------------------
// 1-phase fp16 GEMM -> fp16 out (projections)
// ---------------------------------------------------------------------------
__global__ void __launch_bounds__(256, 2)
gemm_f16(const __half* __restrict__ A, const __half* __restrict__ B,
         __half* __restrict__ Hf,
         int K, int lda, int ldb, int ldc,
         long long aSB, long long bSB, long long cSB, int H)
{
    extern __shared__ char smem[];
    const uint32_t sbase = smem_u32(smem);
    const int tid = threadIdx.x;
    const int wid = tid >> 5;
    const int lid = tid & 31;

    const int zb = blockIdx.z / H;
    const int rowBase = blockIdx.y * BM;
    const int colBase = blockIdx.x * BN;

    const __half* A_ = A + zb * aSB + (long long)rowBase * lda;
    const __half* B_ = B + zb * bSB + (long long)colBase * ldb;
    const long long cOff = zb * cSB;

    const int warpM = (wid >> 2) * 64;
    const int warpN = (wid & 3) * 32;

    float acc[4][4][4];
#pragma unroll
    for (int i = 0; i < 4; i++)
#pragma unroll
        for (int j = 0; j < 4; j++)
#pragma unroll
            for (int v = 0; v < 4; v++) acc[i][j][v] = 0.0f;

    const int nK = K >> 6;

    auto load_stage = [&](int t, int buf) {
        const int k0 = t << 6;
        const uint32_t sS = sbase + buf * STAGE2_B;
        const __half* src[2] = {A_, B_};
        const int lds[2] = {lda, ldb};
#pragma unroll
        for (int tl = 0; tl < 2; tl++) {
            const __half* Q = src[tl];
            const int ld = lds[tl];
            const uint32_t tb = sS + tl * TILE_B;
#pragma unroll
            for (int j = 0; j < 4; j++) {
                int idx = tid + j * 256;
                int row = idx >> 3;
                int c = idx & 7;
                int sw = c ^ (row & 7);
                cp16(tb + row * 128 + sw * 16,
                     Q + (long long)row * ld + k0 + c * 8);
            }
        }
    };

#pragma unroll
    for (int s = 0; s < STAGES; s++) {
        if (s < nK) load_stage(s, s);
        CP_COMMIT();
    }

    for (int t = 0; t < nK; t++) {
        const int buf = t % STAGES;
        CP_WAIT2();
        __syncthreads();

        const uint32_t sS = sbase + buf * STAGE2_B;
        const uint32_t sA = sS;
        const uint32_t sB = sS + TILE_B;

#pragma unroll
        for (int ks = 0; ks < 4; ks++) {
            uint32_t a[4][4], b[2][4];
#pragma unroll
            for (int i = 0; i < 4; i++)
                ldsm4(a[i], frag_addr(sA, warpM + i * 16, ks, lid));
#pragma unroll
            for (int j = 0; j < 2; j++)
                ldsm4(b[j], frag_addr(sB, warpN + j * 16, ks, lid));

#pragma unroll
            for (int i = 0; i < 4; i++)
#pragma unroll
                for (int j = 0; j < 4; j++)
                    mma_f16(acc[i][j], a[i],
                            b[j >> 1][j & 1], b[j >> 1][(j & 1) + 2]);
        }
        __syncthreads();

        const int nt = t + STAGES;
        if (nt < nK) load_stage(nt, buf);
        CP_COMMIT();
    }

    const int g = lid >> 2;
    const int tq = lid & 3;
#pragma unroll
    for (int i = 0; i < 4; i++) {
        const long long r0 = rowBase + warpM + i * 16 + g;
        const long long r1 = r0 + 8;
#pragma unroll
        for (int j = 0; j < 4; j++) {
            const int col = colBase + warpN + j * 8 + tq * 2;
            *reinterpret_cast<__half2*>(Hf + cOff + r0 * ldc + col) =
                __floats2half2_rn(acc[i][j][0], acc[i][j][1]);
            *reinterpret_cast<__half2*>(Hf + cOff + r1 * ldc + col) =
                __floats2half2_rn(acc[i][j][2], acc[i][j][3]);
        }
    }
}

// ---------------------------------------------------------------------------
// fp32 -> fp16 splits
// ---------------------------------------------------------------------------
__global__ void __launch_bounds__(256)
split2_f16(const float* __restrict__ x, __half* __restrict__ h,
           __half* __restrict__ l, long long n4)
{
    long long i = (long long)blockIdx.x * blockDim.x + threadIdx.x;
    if (i >= n4) return;
    float4 v = reinterpret_cast<const float4*>(x)[i];
    __half h0 = __float2half(v.x), h1 = __float2half(v.y);
    __half h2 = __float2half(v.z), h3 = __float2half(v.w);
    __half2 a, b;
    a.x = h0; a.y = h1; b.x = h2; b.y = h3;
    reinterpret_cast<__half2*>(h)[2 * i] = a;
    reinterpret_cast<__half2*>(h)[2 * i + 1] = b;
    a.x = __float2half(v.x - __half2float(h0));
    a.y = __float2half(v.y - __half2float(h1));
    b.x = __float2half(v.z - __half2float(h2));
    b.y = __float2half(v.w - __half2float(h3));
    reinterpret_cast<__half2*>(l)[2 * i] = a;
    reinterpret_cast<__half2*>(l)[2 * i + 1] = b;
}

__global__ void __launch_bounds__(256)
split1_f16(const float* __restrict__ x, __half* __restrict__ h, long long n4)
{
    long long i = (long long)blockIdx.x * blockDim.x + threadIdx.x;
    if (i >= n4) return;
    float4 v = reinterpret_cast<const float4*>(x)[i];
    __half2 a, b;
    a.x = __float2half(v.x); a.y = __float2half(v.y);
    b.x = __float2half(v.z); b.y = __float2half(v.w);
    reinterpret_cast<__half2*>(h)[2 * i] = a;
    reinterpret_cast<__half2*>(h)[2 * i + 1] = b;
}

static void* sym_addr(const void* symbol)
{
    void* p = nullptr;
    cudaGetSymbolAddress(&p, symbol);
    return p;
}

extern "C" void kernel_launch(void* const* d_in, const int* in_sizes, int n_in,
                              void* d_out, int out_size)
{
    const float* X  = (const float*)d_in[0];
    const float* Wq = (const float*)d_in[1];
    const float* Wk = (const float*)d_in[2];
    const float* Wv = (const float*)d_in[3];
    const float* Wo = (const float*)d_in[4];
    float* out = (float*)d_out;

    __half* Xf  = (__half*)sym_addr(g_Xf);
    __half* Wqk = (__half*)sym_addr(g_Wqk);
    __half* Wvf = (__half*)sym_addr(g_Wv);
    __half* Woh = (__half*)sym_addr(g_Woh);
    __half* Wol = (__half*)sym_addr(g_Wol);
    __half* QKb = (__half*)sym_addr(g_QK);
    __half* Vt  = (__half*)sym_addr(g_Vt);
    __half* M   = (__half*)sym_addr(g_M);

    cudaFuncSetAttribute(gemm_2ph, cudaFuncAttributeMaxDynamicSharedMemorySize,
                         G2_SMEM);
    cudaFuncSetAttribute(gemm_f16, cudaFuncAttributeMaxDynamicSharedMemorySize,
                         G1_SMEM);
    cudaFuncSetAttribute(attn_fused, cudaFuncAttributeMaxDynamicSharedMemorySize,
                         AT_SMEM);

    {
        long long n4;
        n4 = (long long)MS * DMODEL / 4;
        split1_f16<<<(unsigned)((n4 + 255) / 256), 256>>>(X, Xf, n4);
        n4 = (long long)DMODEL * DMODEL / 4;
        split1_f16<<<(unsigned)((n4 + 255) / 256), 256>>>(Wq, Wqk, n4);
        split2_f16<<<(unsigned)((n4 + 255) / 256), 256>>>(Wo, Woh, Wol, n4);
        n4 = (long long)DK * DMODEL / 4;
        split1_f16<<<(unsigned)((n4 + 255) / 256), 256>>>(
            Wk, Wqk + (size_t)DMODEL * DMODEL, n4);
        split1_f16<<<(unsigned)((n4 + 255) / 256), 256>>>(Wv, Wvf, n4);
    }

    // QK-proj (merged): QKbuf = Xf @ Wqk^T -> fp16 [8192 x 1280]
    gemm_f16<<<dim3(DQK / BN, MS / BM, 1), 256, G1_SMEM>>>(
        Xf, Wqk, QKb,
        DMODEL, DMODEL, DMODEL, DQK,
        0, 0, 0, 1);

    // VcT[b] = Wv @ Xf[b]^T -> fp16 [256 x 4096] per batch
    gemm_f16<<<dim3(SEQ / BN, DK / BM, BATCH), 256, G1_SMEM>>>(
        Wvf, Xf, Vt,
        DMODEL, DMODEL, DMODEL, SEQ,
        0, (long long)SEQ * DMODEL, (long long)DK * SEQ, 1);

    // fused attention: M = softmax(SCALE * Q K^T) @ V, merged heads
    attn_fused<<<dim3(BATCH * NHEAD, SEQ / QB), 256, AT_SMEM>>>(QKb, Vt, M);

    // out = M @ (Woh + Wol)^T -> fp32
    gemm_2ph<<<dim3(DMODEL / BN, MS / BM, 1), 256, G2_SMEM>>>(
        M, Woh, Wol, out,
        DMODEL, DMODEL, DMODEL, DMODEL);
}

// round 12
// speedup vs baseline: 1.0696x; 1.0696x over previous
#include <cuda_runtime.h>
#include <cuda_fp16.h>
#include <cstdint>
#include <math.h>

#define BATCH 2
#define SEQ   4096
#define DMODEL 1024
#define NHEAD 4
#define DK    256
#define MS (BATCH * SEQ)
#define SCALE_F (1.0f / 16.0f)
#define DQK (DMODEL + DK)          // 1280: merged Q|K projection width

#define BM 128
#define BN 128
#define TILE_B 16384

// 1-phase GEMMs: 2 tiles/stage, 3 stages -> 96KB, 2 CTA/SM
#define STAGES 3
#define STAGE2_B (2 * TILE_B)
#define G1_SMEM (STAGES * STAGE2_B)

// ---------------------------------------------------------------------------
// Device scratch
// ---------------------------------------------------------------------------
__device__ __align__(256) __half g_Xf[(size_t)MS * DMODEL];
__device__ __align__(256) __half g_Wqk[(size_t)DQK * DMODEL];   // Wq rows 0-1023, Wk rows 1024-1279
__device__ __align__(256) __half g_Wv[(size_t)DK * DMODEL];
__device__ __align__(256) __half g_Wo[(size_t)DMODEL * DMODEL];
__device__ __align__(256) __half g_QK[(size_t)MS * DQK];        // Q cols 0-1023, K cols 1024-1279
__device__ __align__(256) __half g_Vt[(size_t)BATCH * DK * SEQ];
__device__ __align__(256) __half g_S[(size_t)BATCH * NHEAD * SEQ * SEQ];
__device__ __align__(256) __half g_M[(size_t)MS * DMODEL];
__device__ __align__(256) float  g_rowsum[(size_t)BATCH * NHEAD * SEQ];

// ---------------------------------------------------------------------------
// PTX helpers
// ---------------------------------------------------------------------------
__device__ __forceinline__ uint32_t smem_u32(const void* p) {
    uint32_t a;
    asm("{ .reg .u64 t; cvta.to.shared.u64 t, %1; cvt.u32.u64 %0, t; }"
        : "=r"(a) : "l"(p));
    return a;
}
__device__ __forceinline__ void cp16(uint32_t s, const void* g) {
    asm volatile("cp.async.cg.shared.global [%0], [%1], 16;" :: "r"(s), "l"(g));
}
#define CP_COMMIT() asm volatile("cp.async.commit_group;" ::: "memory")
#define CP_WAIT2()  asm volatile("cp.async.wait_group 2;" ::: "memory")

__device__ __forceinline__ void ldsm4(uint32_t* r, uint32_t addr) {
    asm volatile("ldmatrix.sync.aligned.m8n8.x4.shared.b16 {%0,%1,%2,%3}, [%4];"
                 : "=r"(r[0]), "=r"(r[1]), "=r"(r[2]), "=r"(r[3]) : "r"(addr));
}
__device__ __forceinline__ void mma_f16(float* c, const uint32_t* a,
                                        uint32_t b0, uint32_t b1) {
    asm volatile(
        "mma.sync.aligned.m16n8k16.row.col.f32.f16.f16.f32 "
        "{%0,%1,%2,%3}, {%4,%5,%6,%7}, {%8,%9}, {%0,%1,%2,%3};\n"
        : "+f"(c[0]), "+f"(c[1]), "+f"(c[2]), "+f"(c[3])
        : "r"(a[0]), "r"(a[1]), "r"(a[2]), "r"(a[3]), "r"(b0), "r"(b1));
}
__device__ __forceinline__ uint32_t frag_addr(uint32_t tbase, int rowBase,
                                              int ks, int lane) {
    int row = rowBase + (lane & 15);
    int chunk = ks * 2 + (lane >> 4);
    int sw = chunk ^ (row & 7);
    return tbase + row * 128 + sw * 16;
}

// ---------------------------------------------------------------------------
// 1-phase fp16 GEMM with fused epilogue variants.
// fuse 0: fp16 out. fuse 1 (QK): out = exp(alpha*acc) fp16, rowsum atomics.
// fuse 2 (PV): out = acc / rowsum[row] fp16. fuse 3: fp32 out.
// ---------------------------------------------------------------------------
__global__ void __launch_bounds__(256, 2)
gemm_f16(const __half* __restrict__ A, const __half* __restrict__ B,
         __half* __restrict__ Hf, float* __restrict__ Cf,
         float* __restrict__ rowsum, int fuse,
         int K, int lda, int ldb, int ldc, float alpha,
         long long aSB, long long aSH, long long bSB, long long bSH,
         long long cSB, long long cSH, int H)
{
    extern __shared__ char smem[];
    const uint32_t sbase = smem_u32(smem);
    const int tid = threadIdx.x;
    const int wid = tid >> 5;
    const int lid = tid & 31;

    const int zb = blockIdx.z / H;
    const int zh = blockIdx.z - zb * H;
    const int rowBase = blockIdx.y * BM;
    const int colBase = blockIdx.x * BN;

    const __half* A_ = A + zb * aSB + zh * aSH + (long long)rowBase * lda;
    const __half* B_ = B + zb * bSB + zh * bSH + (long long)colBase * ldb;
    const long long cOff = zb * cSB + zh * cSH;

    const int warpM = (wid >> 2) * 64;
    const int warpN = (wid & 3) * 32;

    float acc[4][4][4];
#pragma unroll
    for (int i = 0; i < 4; i++)
#pragma unroll
        for (int j = 0; j < 4; j++)
#pragma unroll
            for (int v = 0; v < 4; v++) acc[i][j][v] = 0.0f;

    const int nK = K >> 6;

    auto load_stage = [&](int t, int buf) {
        const int k0 = t << 6;
        const uint32_t sS = sbase + buf * STAGE2_B;
        const __half* src[2] = {A_, B_};
        const int lds[2] = {lda, ldb};
#pragma unroll
        for (int tl = 0; tl < 2; tl++) {
            const __half* Q = src[tl];
            const int ld = lds[tl];
            const uint32_t tb = sS + tl * TILE_B;
#pragma unroll
            for (int j = 0; j < 4; j++) {
                int idx = tid + j * 256;
                int row = idx >> 3;
                int c = idx & 7;
                int sw = c ^ (row & 7);
                cp16(tb + row * 128 + sw * 16,
                     Q + (long long)row * ld + k0 + c * 8);
            }
        }
    };

#pragma unroll
    for (int s = 0; s < STAGES; s++) {
        if (s < nK) load_stage(s, s);
        CP_COMMIT();
    }

    for (int t = 0; t < nK; t++) {
        const int buf = t % STAGES;
        CP_WAIT2();
        __syncthreads();

        const uint32_t sS = sbase + buf * STAGE2_B;
        const uint32_t sA = sS;
        const uint32_t sB = sS + TILE_B;

#pragma unroll
        for (int ks = 0; ks < 4; ks++) {
            uint32_t a[4][4], b[2][4];
#pragma unroll
            for (int i = 0; i < 4; i++)
                ldsm4(a[i], frag_addr(sA, warpM + i * 16, ks, lid));
#pragma unroll
            for (int j = 0; j < 2; j++)
                ldsm4(b[j], frag_addr(sB, warpN + j * 16, ks, lid));

#pragma unroll
            for (int i = 0; i < 4; i++) {
#pragma unroll
                for (int j = 0; j < 4; j++) {
                    mma_f16(acc[i][j], a[i],
                            b[j >> 1][j & 1], b[j >> 1][(j & 1) + 2]);
                }
            }
        }
        __syncthreads();

        const int nt = t + STAGES;
        if (nt < nK) load_stage(nt, buf);
        CP_COMMIT();
    }

    const int g = lid >> 2;
    const int tq = lid & 3;
    const long long sumBase = (long long)blockIdx.z * SEQ;

#pragma unroll
    for (int i = 0; i < 4; i++) {
        const int lr0 = rowBase + warpM + i * 16 + g;
        const int lr1 = lr0 + 8;
        const long long r0 = lr0, r1 = lr1;

        float inv0 = 1.0f, inv1 = 1.0f;
        if (fuse == 2) {
            inv0 = __frcp_rn(rowsum[sumBase + lr0]);
            inv1 = __frcp_rn(rowsum[sumBase + lr1]);
        }
        float se0 = 0.0f, se1 = 0.0f;

#pragma unroll
        for (int j = 0; j < 4; j++) {
            const int col = colBase + warpN + j * 8 + tq * 2;
            float x0 = acc[i][j][0] * alpha, x1 = acc[i][j][1] * alpha;
            float x2 = acc[i][j][2] * alpha, x3 = acc[i][j][3] * alpha;
            if (fuse == 1) {
                x0 = __expf(x0); x1 = __expf(x1);
                x2 = __expf(x2); x3 = __expf(x3);
                se0 += x0 + x1;
                se1 += x2 + x3;
            } else if (fuse == 2) {
                x0 *= inv0; x1 *= inv0;
                x2 *= inv1; x3 *= inv1;
            }
            if (fuse == 3) {
                *reinterpret_cast<float2*>(Cf + cOff + r0 * ldc + col) =
                    make_float2(x0, x1);
                *reinterpret_cast<float2*>(Cf + cOff + r1 * ldc + col) =
                    make_float2(x2, x3);
            } else {
                *reinterpret_cast<__half2*>(Hf + cOff + r0 * ldc + col) =
                    __floats2half2_rn(x0, x1);
                *reinterpret_cast<__half2*>(Hf + cOff + r1 * ldc + col) =
                    __floats2half2_rn(x2, x3);
            }
        }

        if (fuse == 1) {
            se0 += __shfl_xor_sync(0xffffffffu, se0, 1);
            se0 += __shfl_xor_sync(0xffffffffu, se0, 2);
            se1 += __shfl_xor_sync(0xffffffffu, se1, 1);
            se1 += __shfl_xor_sync(0xffffffffu, se1, 2);
            if (tq == 0) {
                atomicAdd(&rowsum[sumBase + lr0], se0);
                atomicAdd(&rowsum[sumBase + lr1], se1);
            }
        }
    }
}

// ---------------------------------------------------------------------------
// fp32 -> fp16 single
// ---------------------------------------------------------------------------
__global__ void __launch_bounds__(256)
split1_f16(const float* __restrict__ x, __half* __restrict__ h, long long n4)
{
    long long i = (long long)blockIdx.x * blockDim.x + threadIdx.x;
    if (i >= n4) return;
    float4 v = reinterpret_cast<const float4*>(x)[i];
    __half2 a, b;
    a.x = __float2half(v.x); a.y = __float2half(v.y);
    b.x = __float2half(v.z); b.y = __float2half(v.w);
    reinterpret_cast<__half2*>(h)[2 * i] = a;
    reinterpret_cast<__half2*>(h)[2 * i + 1] = b;
}

static void* sym_addr(const void* symbol)
{
    void* p = nullptr;
    cudaGetSymbolAddress(&p, symbol);
    return p;
}

extern "C" void kernel_launch(void* const* d_in, const int* in_sizes, int n_in,
                              void* d_out, int out_size)
{
    const float* X  = (const float*)d_in[0];
    const float* Wq = (const float*)d_in[1];
    const float* Wk = (const float*)d_in[2];
    const float* Wv = (const float*)d_in[3];
    const float* Wo = (const float*)d_in[4];
    float* out = (float*)d_out;

    __half* Xf  = (__half*)sym_addr(g_Xf);
    __half* Wqk = (__half*)sym_addr(g_Wqk);
    __half* Wvf = (__half*)sym_addr(g_Wv);
    __half* Wof = (__half*)sym_addr(g_Wo);
    __half* QKb = (__half*)sym_addr(g_QK);
    __half* Vt  = (__half*)sym_addr(g_Vt);
    __half* S   = (__half*)sym_addr(g_S);
    __half* M   = (__half*)sym_addr(g_M);
    float*  rs  = (float*)sym_addr(g_rowsum);

    cudaFuncSetAttribute(gemm_f16, cudaFuncAttributeMaxDynamicSharedMemorySize,
                         G1_SMEM);

    cudaMemsetAsync(rs, 0, (size_t)BATCH * NHEAD * SEQ * sizeof(float));

    {
        long long n4;
        n4 = (long long)MS * DMODEL / 4;
        split1_f16<<<(unsigned)((n4 + 255) / 256), 256>>>(X, Xf, n4);
        n4 = (long long)DMODEL * DMODEL / 4;
        split1_f16<<<(unsigned)((n4 + 255) / 256), 256>>>(Wq, Wqk, n4);
        split1_f16<<<(unsigned)((n4 + 255) / 256), 256>>>(Wo, Wof, n4);
        n4 = (long long)DK * DMODEL / 4;
        split1_f16<<<(unsigned)((n4 + 255) / 256), 256>>>(
            Wk, Wqk + (size_t)DMODEL * DMODEL, n4);
        split1_f16<<<(unsigned)((n4 + 255) / 256), 256>>>(Wv, Wvf, n4);
    }

    // QK-proj (merged): QKbuf = Xf @ Wqk^T -> fp16 [8192 x 1280]
    gemm_f16<<<dim3(DQK / BN, MS / BM, 1), 256, G1_SMEM>>>(
        Xf, Wqk, QKb, nullptr, rs, 0,
        DMODEL, DMODEL, DMODEL, DQK, 1.0f,
        0, 0, 0, 0, 0, 0, 1);

    // VcT[b] = Wv @ Xf[b]^T -> fp16 [256 x 4096] per batch
    gemm_f16<<<dim3(SEQ / BN, DK / BM, BATCH), 256, G1_SMEM>>>(
        Wvf, Xf, Vt, nullptr, rs, 0,
        DMODEL, DMODEL, DMODEL, SEQ, 1.0f,
        0, 0, (long long)SEQ * DMODEL, 0,
        (long long)DK * SEQ, 0, 1);

    // S[b,h] = exp(SCALE * Q[b,h] @ K[b]^T) -> fp16, rowsum accumulated
    gemm_f16<<<dim3(SEQ / BN, SEQ / BM, BATCH * NHEAD), 256, G1_SMEM>>>(
        QKb, QKb + DMODEL, S, nullptr, rs, 1,
        DK, DQK, DQK, SEQ, SCALE_F,
        (long long)SEQ * DQK, DK,
        (long long)SEQ * DQK, 0,
        (long long)NHEAD * SEQ * SEQ, (long long)SEQ * SEQ, NHEAD);

    // M = (S @ VcT^T) / rowsum -> fp16 merged [8192 x 1024]
    gemm_f16<<<dim3(DK / BN, SEQ / BM, BATCH * NHEAD), 256, G1_SMEM>>>(
        S, Vt, M, nullptr, rs, 2,
        SEQ, SEQ, SEQ, DMODEL, 1.0f,
        (long long)NHEAD * SEQ * SEQ, (long long)SEQ * SEQ,
        (long long)DK * SEQ, 0,
        (long long)SEQ * DMODEL, DK, NHEAD);

    // out = M @ Wo^T -> fp32 (1-phase)
    gemm_f16<<<dim3(DMODEL / BN, MS / BM, 1), 256, G1_SMEM>>>(
        M, Wof, nullptr, out, rs, 3,
        DMODEL, DMODEL, DMODEL, DMODEL, 1.0f,
        0, 0, 0, 0, 0, 0, 1);
}

// round 13
// speedup vs baseline: 1.0802x; 1.0100x over previous
#include <cuda_runtime.h>
#include <cuda_fp16.h>
#include <cstdint>
#include <math.h>

#define BATCH 2
#define SEQ   4096
#define DMODEL 1024
#define NHEAD 4
#define DK    256
#define MS (BATCH * SEQ)
#define SCALE_F (1.0f / 16.0f)
#define DQK (DMODEL + DK)          // 1280: merged Q|K projection width

#define BM 128
#define BN 128
#define TILE_B 16384

// 1-phase GEMMs: 2 tiles/stage, 3 stages -> 96KB, 2 CTA/SM
#define STAGES 3
#define STAGE2_B (2 * TILE_B)
#define G1_SMEM (STAGES * STAGE2_B)

// ---------------------------------------------------------------------------
// Device scratch
// ---------------------------------------------------------------------------
__device__ __align__(256) __half g_Xf[(size_t)MS * DMODEL];
__device__ __align__(256) __half g_Wqk[(size_t)DQK * DMODEL];   // Wq rows 0-1023, Wk rows 1024-1279
__device__ __align__(256) __half g_Wv[(size_t)DK * DMODEL];
__device__ __align__(256) __half g_Wo[(size_t)DMODEL * DMODEL];
__device__ __align__(256) __half g_QK[(size_t)MS * DQK];        // Q cols 0-1023, K cols 1024-1279
__device__ __align__(256) __half g_Vt[(size_t)BATCH * DK * SEQ];
__device__ __align__(256) __half g_S[(size_t)BATCH * NHEAD * SEQ * SEQ];
__device__ __align__(256) __half g_M[(size_t)MS * DMODEL];
__device__ __align__(256) float  g_rowsum[(size_t)BATCH * NHEAD * SEQ];

// ---------------------------------------------------------------------------
// PTX helpers
// ---------------------------------------------------------------------------
__device__ __forceinline__ uint32_t smem_u32(const void* p) {
    uint32_t a;
    asm("{ .reg .u64 t; cvta.to.shared.u64 t, %1; cvt.u32.u64 %0, t; }"
        : "=r"(a) : "l"(p));
    return a;
}
__device__ __forceinline__ void cp16(uint32_t s, const void* g) {
    asm volatile("cp.async.cg.shared.global [%0], [%1], 16;" :: "r"(s), "l"(g));
}
#define CP_COMMIT() asm volatile("cp.async.commit_group;" ::: "memory")
#define CP_WAIT2()  asm volatile("cp.async.wait_group 2;" ::: "memory")

__device__ __forceinline__ void ldsm4(uint32_t* r, uint32_t addr) {
    asm volatile("ldmatrix.sync.aligned.m8n8.x4.shared.b16 {%0,%1,%2,%3}, [%4];"
                 : "=r"(r[0]), "=r"(r[1]), "=r"(r[2]), "=r"(r[3]) : "r"(addr));
}
__device__ __forceinline__ void mma_f16(float* c, const uint32_t* a,
                                        uint32_t b0, uint32_t b1) {
    asm volatile(
        "mma.sync.aligned.m16n8k16.row.col.f32.f16.f16.f32 "
        "{%0,%1,%2,%3}, {%4,%5,%6,%7}, {%8,%9}, {%0,%1,%2,%3};\n"
        : "+f"(c[0]), "+f"(c[1]), "+f"(c[2]), "+f"(c[3])
        : "r"(a[0]), "r"(a[1]), "r"(a[2]), "r"(a[3]), "r"(b0), "r"(b1));
}
__device__ __forceinline__ uint32_t frag_addr(uint32_t tbase, int rowBase,
                                              int ks, int lane) {
    int row = rowBase + (lane & 15);
    int chunk = ks * 2 + (lane >> 4);
    int sw = chunk ^ (row & 7);
    return tbase + row * 128 + sw * 16;
}

// ---------------------------------------------------------------------------
// Shared GEMM body: 1-phase fp16, 128x128 tile, 3-stage cp.async pipeline.
// fuse 0: fp16 out. fuse 1: out = exp(alpha*acc) fp16 + rowsum atomics.
// fuse 2: out = acc / rowsum[row] fp16. fuse 3: fp32 out.
// A_/B_ pre-offset by row/col base; Hf/Cf/rowsum pre-offset by batch.
// ---------------------------------------------------------------------------
__device__ __forceinline__ void gemm_body(
    const __half* __restrict__ A_, const __half* __restrict__ B_,
    __half* __restrict__ Hf, float* __restrict__ Cf,
    float* __restrict__ rowsum, int fuse,
    int nK, int lda, int ldb, int ldc, float alpha,
    int rowBase, int colBase, uint32_t sbase)
{
    const int tid = threadIdx.x;
    const int wid = tid >> 5;
    const int lid = tid & 31;
    const int warpM = (wid >> 2) * 64;
    const int warpN = (wid & 3) * 32;

    float acc[4][4][4];
#pragma unroll
    for (int i = 0; i < 4; i++)
#pragma unroll
        for (int j = 0; j < 4; j++)
#pragma unroll
            for (int v = 0; v < 4; v++) acc[i][j][v] = 0.0f;

    auto load_stage = [&](int t, int buf) {
        const int k0 = t << 6;
        const uint32_t sS = sbase + buf * STAGE2_B;
        const __half* src[2] = {A_, B_};
        const int lds[2] = {lda, ldb};
#pragma unroll
        for (int tl = 0; tl < 2; tl++) {
            const __half* Q = src[tl];
            const int ld = lds[tl];
            const uint32_t tb = sS + tl * TILE_B;
#pragma unroll
            for (int j = 0; j < 4; j++) {
                int idx = tid + j * 256;
                int row = idx >> 3;
                int c = idx & 7;
                int sw = c ^ (row & 7);
                cp16(tb + row * 128 + sw * 16,
                     Q + (long long)row * ld + k0 + c * 8);
            }
        }
    };

#pragma unroll
    for (int s = 0; s < STAGES; s++) {
        if (s < nK) load_stage(s, s);
        CP_COMMIT();
    }

    for (int t = 0; t < nK; t++) {
        const int buf = t % STAGES;
        CP_WAIT2();
        __syncthreads();

        const uint32_t sS = sbase + buf * STAGE2_B;
        const uint32_t sA = sS;
        const uint32_t sB = sS + TILE_B;

#pragma unroll
        for (int ks = 0; ks < 4; ks++) {
            uint32_t a[4][4], b[2][4];
#pragma unroll
            for (int i = 0; i < 4; i++)
                ldsm4(a[i], frag_addr(sA, warpM + i * 16, ks, lid));
#pragma unroll
            for (int j = 0; j < 2; j++)
                ldsm4(b[j], frag_addr(sB, warpN + j * 16, ks, lid));

#pragma unroll
            for (int i = 0; i < 4; i++) {
#pragma unroll
                for (int j = 0; j < 4; j++) {
                    mma_f16(acc[i][j], a[i],
                            b[j >> 1][j & 1], b[j >> 1][(j & 1) + 2]);
                }
            }
        }
        __syncthreads();

        const int nt = t + STAGES;
        if (nt < nK) load_stage(nt, buf);
        CP_COMMIT();
    }

    const int g = lid >> 2;
    const int tq = lid & 3;

#pragma unroll
    for (int i = 0; i < 4; i++) {
        const int lr0 = rowBase + warpM + i * 16 + g;
        const int lr1 = lr0 + 8;
        const long long r0 = lr0, r1 = lr1;

        float inv0 = 1.0f, inv1 = 1.0f;
        if (fuse == 2) {
            inv0 = __frcp_rn(rowsum[lr0]);
            inv1 = __frcp_rn(rowsum[lr1]);
        }
        float se0 = 0.0f, se1 = 0.0f;

#pragma unroll
        for (int j = 0; j < 4; j++) {
            const int col = colBase + warpN + j * 8 + tq * 2;
            float x0 = acc[i][j][0] * alpha, x1 = acc[i][j][1] * alpha;
            float x2 = acc[i][j][2] * alpha, x3 = acc[i][j][3] * alpha;
            if (fuse == 1) {
                x0 = __expf(x0); x1 = __expf(x1);
                x2 = __expf(x2); x3 = __expf(x3);
                se0 += x0 + x1;
                se1 += x2 + x3;
            } else if (fuse == 2) {
                x0 *= inv0; x1 *= inv0;
                x2 *= inv1; x3 *= inv1;
            }
            if (fuse == 3) {
                *reinterpret_cast<float2*>(Cf + r0 * ldc + col) =
                    make_float2(x0, x1);
                *reinterpret_cast<float2*>(Cf + r1 * ldc + col) =
                    make_float2(x2, x3);
            } else {
                *reinterpret_cast<__half2*>(Hf + r0 * ldc + col) =
                    __floats2half2_rn(x0, x1);
                *reinterpret_cast<__half2*>(Hf + r1 * ldc + col) =
                    __floats2half2_rn(x2, x3);
            }
        }

        if (fuse == 1) {
            se0 += __shfl_xor_sync(0xffffffffu, se0, 1);
            se0 += __shfl_xor_sync(0xffffffffu, se0, 2);
            se1 += __shfl_xor_sync(0xffffffffu, se1, 1);
            se1 += __shfl_xor_sync(0xffffffffu, se1, 2);
            if (tq == 0) {
                atomicAdd(&rowsum[lr0], se0);
                atomicAdd(&rowsum[lr1], se1);
            }
        }
    }
}

// ---------------------------------------------------------------------------
// Generic batched GEMM kernel (QK, PV, O-proj)
// ---------------------------------------------------------------------------
__global__ void __launch_bounds__(256, 2)
gemm_f16(const __half* __restrict__ A, const __half* __restrict__ B,
         __half* __restrict__ Hf, float* __restrict__ Cf,
         float* __restrict__ rowsum, int fuse,
         int K, int lda, int ldb, int ldc, float alpha,
         long long aSB, long long aSH, long long bSB, long long bSH,
         long long cSB, long long cSH, int H)
{
    extern __shared__ char smem[];
    const uint32_t sbase = smem_u32(smem);

    const int zb = blockIdx.z / H;
    const int zh = blockIdx.z - zb * H;
    const int rowBase = blockIdx.y * BM;
    const int colBase = blockIdx.x * BN;

    const __half* A_ = A + zb * aSB + zh * aSH + (long long)rowBase * lda;
    const __half* B_ = B + zb * bSB + zh * bSH + (long long)colBase * ldb;
    const long long cOff = zb * cSB + zh * cSH;

    gemm_body(A_, B_,
              Hf ? Hf + cOff : nullptr,
              Cf ? Cf + cOff : nullptr,
              rowsum + (long long)blockIdx.z * SEQ, fuse,
              K >> 6, lda, ldb, ldc, alpha, rowBase, colBase, sbase);
}

// ---------------------------------------------------------------------------
// Merged projection kernel: one launch covers QK-proj and V-proj.
//   bid <  640: QK-proj  QKbuf = Xf @ Wqk^T  (grid 10 x 64)
//   bid >= 640: V-proj   Vt[b] = Wv @ Xf[b]^T (2 batches x (32 x 2))
// ---------------------------------------------------------------------------
__global__ void __launch_bounds__(256, 2)
proj_merged(const __half* __restrict__ Xf, const __half* __restrict__ Wqk,
            const __half* __restrict__ Wv, __half* __restrict__ QKb,
            __half* __restrict__ Vt)
{
    extern __shared__ char smem[];
    const uint32_t sbase = smem_u32(smem);
    const int bid = blockIdx.x;

    if (bid < 640) {
        const int x = bid % (DQK / BN);       // 0..9
        const int y = bid / (DQK / BN);       // 0..63
        const int rowBase = y * BM;
        const int colBase = x * BN;
        gemm_body(Xf + (long long)rowBase * DMODEL,
                  Wqk + (long long)colBase * DMODEL,
                  QKb, nullptr, nullptr, 0,
                  DMODEL >> 6, DMODEL, DMODEL, DQK, 1.0f,
                  rowBase, colBase, sbase);
    } else {
        const int t = bid - 640;
        const int zb = t / 64;                // batch
        const int rem = t - zb * 64;
        const int x = rem % (SEQ / BN);       // 0..31
        const int y = rem / (SEQ / BN);       // 0..1
        const int rowBase = y * BM;
        const int colBase = x * BN;
        gemm_body(Wv + (long long)rowBase * DMODEL,
                  Xf + (long long)zb * SEQ * DMODEL + (long long)colBase * DMODEL,
                  Vt + (long long)zb * DK * SEQ, nullptr, nullptr, 0,
                  DMODEL >> 6, DMODEL, DMODEL, SEQ, 1.0f,
                  rowBase, colBase, sbase);
    }
}

// ---------------------------------------------------------------------------
// Merged split kernel: all fp32->fp16 conversions + rowsum zeroing, 1 launch.
// Each block handles 256 float4s (1024 floats) of one segment.
//   [0, 8192)        X  -> Xf
//   [8192, 9216)     Wq -> Wqk rows 0-1023
//   [9216, 9472)     Wk -> Wqk rows 1024-1279
//   [9472, 9728)     Wv -> Wvf
//   [9728, 10752)    Wo -> Wof
//   [10752, 10784)   zero g_rowsum (32768 floats as float4)
// ---------------------------------------------------------------------------
__global__ void __launch_bounds__(256)
split_all(const float* __restrict__ X,  const float* __restrict__ Wq,
          const float* __restrict__ Wk, const float* __restrict__ Wv,
          const float* __restrict__ Wo,
          __half* __restrict__ Xf, __half* __restrict__ Wqk,
          __half* __restrict__ Wvf, __half* __restrict__ Wof,
          float* __restrict__ rowsum)
{
    const int bid = blockIdx.x;
    const int tid = threadIdx.x;

    const float* src;
    __half* dst;
    long long i;   // float4 index within segment

    if (bid < 8192) {
        src = X;  dst = Xf;  i = (long long)bid * 256 + tid;
    } else if (bid < 9216) {
        src = Wq; dst = Wqk; i = (long long)(bid - 8192) * 256 + tid;
    } else if (bid < 9472) {
        src = Wk; dst = Wqk + (size_t)DMODEL * DMODEL;
        i = (long long)(bid - 9216) * 256 + tid;
    } else if (bid < 9728) {
        src = Wv; dst = Wvf; i = (long long)(bid - 9472) * 256 + tid;
    } else if (bid < 10752) {
        src = Wo; dst = Wof; i = (long long)(bid - 9728) * 256 + tid;
    } else {
        long long z = (long long)(bid - 10752) * 256 + tid;
        reinterpret_cast<float4*>(rowsum)[z] = make_float4(0.f, 0.f, 0.f, 0.f);
        return;
    }

    float4 v = reinterpret_cast<const float4*>(src)[i];
    __half2 a, b;
    a.x = __float2half(v.x); a.y = __float2half(v.y);
    b.x = __float2half(v.z); b.y = __float2half(v.w);
    reinterpret_cast<__half2*>(dst)[2 * i] = a;
    reinterpret_cast<__half2*>(dst)[2 * i + 1] = b;
}

static void* sym_addr(const void* symbol)
{
    void* p = nullptr;
    cudaGetSymbolAddress(&p, symbol);
    return p;
}

extern "C" void kernel_launch(void* const* d_in, const int* in_sizes, int n_in,
                              void* d_out, int out_size)
{
    const float* X  = (const float*)d_in[0];
    const float* Wq = (const float*)d_in[1];
    const float* Wk = (const float*)d_in[2];
    const float* Wv = (const float*)d_in[3];
    const float* Wo = (const float*)d_in[4];
    float* out = (float*)d_out;

    __half* Xf  = (__half*)sym_addr(g_Xf);
    __half* Wqk = (__half*)sym_addr(g_Wqk);
    __half* Wvf = (__half*)sym_addr(g_Wv);
    __half* Wof = (__half*)sym_addr(g_Wo);
    __half* QKb = (__half*)sym_addr(g_QK);
    __half* Vt  = (__half*)sym_addr(g_Vt);
    __half* S   = (__half*)sym_addr(g_S);
    __half* M   = (__half*)sym_addr(g_M);
    float*  rs  = (float*)sym_addr(g_rowsum);

    cudaFuncSetAttribute(gemm_f16, cudaFuncAttributeMaxDynamicSharedMemorySize,
                         G1_SMEM);
    cudaFuncSetAttribute(proj_merged, cudaFuncAttributeMaxDynamicSharedMemorySize,
                         G1_SMEM);

    // 1 launch: all fp32->fp16 splits + rowsum zeroing
    split_all<<<10784, 256>>>(X, Wq, Wk, Wv, Wo, Xf, Wqk, Wvf, Wof, rs);

    // 1 launch: QK-proj (merged Q|K) + V-proj
    proj_merged<<<768, 256, G1_SMEM>>>(Xf, Wqk, Wvf, QKb, Vt);

    // S[b,h] = exp(SCALE * Q[b,h] @ K[b]^T) -> fp16, rowsum accumulated
    gemm_f16<<<dim3(SEQ / BN, SEQ / BM, BATCH * NHEAD), 256, G1_SMEM>>>(
        QKb, QKb + DMODEL, S, nullptr, rs, 1,
        DK, DQK, DQK, SEQ, SCALE_F,
        (long long)SEQ * DQK, DK,
        (long long)SEQ * DQK, 0,
        (long long)NHEAD * SEQ * SEQ, (long long)SEQ * SEQ, NHEAD);

    // M = (S @ VcT^T) / rowsum -> fp16 merged [8192 x 1024]
    gemm_f16<<<dim3(DK / BN, SEQ / BM, BATCH * NHEAD), 256, G1_SMEM>>>(
        S, Vt, M, nullptr, rs, 2,
        SEQ, SEQ, SEQ, DMODEL, 1.0f,
        (long long)NHEAD * SEQ * SEQ, (long long)SEQ * SEQ,
        (long long)DK * SEQ, 0,
        (long long)SEQ * DMODEL, DK, NHEAD);

    // out = M @ Wo^T -> fp32 (1-phase)
    gemm_f16<<<dim3(DMODEL / BN, MS / BM, 1), 256, G1_SMEM>>>(
        M, Wof, nullptr, out, rs, 3,
        DMODEL, DMODEL, DMODEL, DMODEL, 1.0f,
        0, 0, 0, 0, 0, 0, 1);
}

// round 14
// speedup vs baseline: 1.1411x; 1.0564x over previous
#include <cuda_runtime.h>
#include <cuda_fp16.h>
#include <cstdint>
#include <math.h>

#define BATCH 2
#define SEQ   4096
#define DMODEL 1024
#define NHEAD 4
#define DK    256
#define MS (BATCH * SEQ)
#define SCALE_F (1.0f / 16.0f)
#define DQK (DMODEL + DK)          // 1280: merged Q|K projection width

#define BM 128
#define BN 128
#define TILE_B 16384
#define NTHREADS 128               // 4 warps, 2x2 warp grid, 64x64 warp tile

// 1-phase GEMMs: 2 tiles/stage, 3 stages -> 96KB, 2 CTA/SM
#define STAGES 3
#define STAGE2_B (2 * TILE_B)
#define G1_SMEM (STAGES * STAGE2_B)

// ---------------------------------------------------------------------------
// Device scratch
// ---------------------------------------------------------------------------
__device__ __align__(256) __half g_Xf[(size_t)MS * DMODEL];
__device__ __align__(256) __half g_Wqk[(size_t)DQK * DMODEL];   // Wq rows 0-1023, Wk rows 1024-1279
__device__ __align__(256) __half g_Wv[(size_t)DK * DMODEL];
__device__ __align__(256) __half g_Wo[(size_t)DMODEL * DMODEL];
__device__ __align__(256) __half g_QK[(size_t)MS * DQK];        // Q cols 0-1023, K cols 1024-1279
__device__ __align__(256) __half g_Vt[(size_t)BATCH * DK * SEQ];
__device__ __align__(256) __half g_S[(size_t)BATCH * NHEAD * SEQ * SEQ];
__device__ __align__(256) __half g_M[(size_t)MS * DMODEL];
__device__ __align__(256) float  g_rowsum[(size_t)BATCH * NHEAD * SEQ];

// ---------------------------------------------------------------------------
// PTX helpers
// ---------------------------------------------------------------------------
__device__ __forceinline__ uint32_t smem_u32(const void* p) {
    uint32_t a;
    asm("{ .reg .u64 t; cvta.to.shared.u64 t, %1; cvt.u32.u64 %0, t; }"
        : "=r"(a) : "l"(p));
    return a;
}
__device__ __forceinline__ void cp16(uint32_t s, const void* g) {
    asm volatile("cp.async.cg.shared.global [%0], [%1], 16;" :: "r"(s), "l"(g));
}
#define CP_COMMIT() asm volatile("cp.async.commit_group;" ::: "memory")
#define CP_WAIT2()  asm volatile("cp.async.wait_group 2;" ::: "memory")

__device__ __forceinline__ void ldsm4(uint32_t* r, uint32_t addr) {
    asm volatile("ldmatrix.sync.aligned.m8n8.x4.shared.b16 {%0,%1,%2,%3}, [%4];"
                 : "=r"(r[0]), "=r"(r[1]), "=r"(r[2]), "=r"(r[3]) : "r"(addr));
}
__device__ __forceinline__ void mma_f16(float* c, const uint32_t* a,
                                        uint32_t b0, uint32_t b1) {
    asm volatile(
        "mma.sync.aligned.m16n8k16.row.col.f32.f16.f16.f32 "
        "{%0,%1,%2,%3}, {%4,%5,%6,%7}, {%8,%9}, {%0,%1,%2,%3};\n"
        : "+f"(c[0]), "+f"(c[1]), "+f"(c[2]), "+f"(c[3])
        : "r"(a[0]), "r"(a[1]), "r"(a[2]), "r"(a[3]), "r"(b0), "r"(b1));
}
__device__ __forceinline__ uint32_t frag_addr(uint32_t tbase, int rowBase,
                                              int ks, int lane) {
    int row = rowBase + (lane & 15);
    int chunk = ks * 2 + (lane >> 4);
    int sw = chunk ^ (row & 7);
    return tbase + row * 128 + sw * 16;
}

// ---------------------------------------------------------------------------
// Shared GEMM body: 1-phase fp16, 128x128 CTA tile, 4 warps (64x64 warp tile),
// 3-stage cp.async pipeline.
// fuse 0: fp16 out. fuse 1: out = exp(alpha*acc) fp16 + rowsum atomics.
// fuse 2: out = acc / rowsum[row] fp16. fuse 3: fp32 out.
// A_/B_ pre-offset by row/col base; Hf/Cf/rowsum pre-offset by batch.
// ---------------------------------------------------------------------------
__device__ __forceinline__ void gemm_body(
    const __half* __restrict__ A_, const __half* __restrict__ B_,
    __half* __restrict__ Hf, float* __restrict__ Cf,
    float* __restrict__ rowsum, int fuse,
    int nK, int lda, int ldb, int ldc, float alpha,
    int rowBase, int colBase, uint32_t sbase)
{
    const int tid = threadIdx.x;
    const int wid = tid >> 5;          // 0..3
    const int lid = tid & 31;
    const int warpM = (wid >> 1) * 64; // 2x2 warp grid
    const int warpN = (wid & 1) * 64;

    float acc[4][8][4];
#pragma unroll
    for (int i = 0; i < 4; i++)
#pragma unroll
        for (int j = 0; j < 8; j++)
#pragma unroll
            for (int v = 0; v < 4; v++) acc[i][j][v] = 0.0f;

    auto load_stage = [&](int t, int buf) {
        const int k0 = t << 6;
        const uint32_t sS = sbase + buf * STAGE2_B;
        const __half* src[2] = {A_, B_};
        const int lds[2] = {lda, ldb};
#pragma unroll
        for (int tl = 0; tl < 2; tl++) {
            const __half* Q = src[tl];
            const int ld = lds[tl];
            const uint32_t tb = sS + tl * TILE_B;
#pragma unroll
            for (int j = 0; j < 8; j++) {
                int idx = tid + j * NTHREADS;   // 0..1023
                int row = idx >> 3;
                int c = idx & 7;
                int sw = c ^ (row & 7);
                cp16(tb + row * 128 + sw * 16,
                     Q + (long long)row * ld + k0 + c * 8);
            }
        }
    };

#pragma unroll
    for (int s = 0; s < STAGES; s++) {
        if (s < nK) load_stage(s, s);
        CP_COMMIT();
    }

    for (int t = 0; t < nK; t++) {
        const int buf = t % STAGES;
        CP_WAIT2();
        __syncthreads();

        const uint32_t sS = sbase + buf * STAGE2_B;
        const uint32_t sA = sS;
        const uint32_t sB = sS + TILE_B;

#pragma unroll
        for (int ks = 0; ks < 4; ks++) {
            uint32_t a[4][4], b[4][4];
#pragma unroll
            for (int i = 0; i < 4; i++)
                ldsm4(a[i], frag_addr(sA, warpM + i * 16, ks, lid));
#pragma unroll
            for (int jg = 0; jg < 4; jg++)
                ldsm4(b[jg], frag_addr(sB, warpN + jg * 16, ks, lid));

#pragma unroll
            for (int i = 0; i < 4; i++) {
#pragma unroll
                for (int j = 0; j < 8; j++) {
                    mma_f16(acc[i][j], a[i],
                            b[j >> 1][j & 1], b[j >> 1][(j & 1) + 2]);
                }
            }
        }
        __syncthreads();

        const int nt = t + STAGES;
        if (nt < nK) load_stage(nt, buf);
        CP_COMMIT();
    }

    const int g = lid >> 2;
    const int tq = lid & 3;

#pragma unroll
    for (int i = 0; i < 4; i++) {
        const int lr0 = rowBase + warpM + i * 16 + g;
        const int lr1 = lr0 + 8;
        const long long r0 = lr0, r1 = lr1;

        float inv0 = 1.0f, inv1 = 1.0f;
        if (fuse == 2) {
            inv0 = __frcp_rn(rowsum[lr0]);
            inv1 = __frcp_rn(rowsum[lr1]);
        }
        float se0 = 0.0f, se1 = 0.0f;

#pragma unroll
        for (int j = 0; j < 8; j++) {
            const int col = colBase + warpN + j * 8 + tq * 2;
            float x0 = acc[i][j][0] * alpha, x1 = acc[i][j][1] * alpha;
            float x2 = acc[i][j][2] * alpha, x3 = acc[i][j][3] * alpha;
            if (fuse == 1) {
                x0 = __expf(x0); x1 = __expf(x1);
                x2 = __expf(x2); x3 = __expf(x3);
                se0 += x0 + x1;
                se1 += x2 + x3;
            } else if (fuse == 2) {
                x0 *= inv0; x1 *= inv0;
                x2 *= inv1; x3 *= inv1;
            }
            if (fuse == 3) {
                *reinterpret_cast<float2*>(Cf + r0 * ldc + col) =
                    make_float2(x0, x1);
                *reinterpret_cast<float2*>(Cf + r1 * ldc + col) =
                    make_float2(x2, x3);
            } else {
                *reinterpret_cast<__half2*>(Hf + r0 * ldc + col) =
                    __floats2half2_rn(x0, x1);
                *reinterpret_cast<__half2*>(Hf + r1 * ldc + col) =
                    __floats2half2_rn(x2, x3);
            }
        }

        if (fuse == 1) {
            se0 += __shfl_xor_sync(0xffffffffu, se0, 1);
            se0 += __shfl_xor_sync(0xffffffffu, se0, 2);
            se1 += __shfl_xor_sync(0xffffffffu, se1, 1);
            se1 += __shfl_xor_sync(0xffffffffu, se1, 2);
            if (tq == 0) {
                atomicAdd(&rowsum[lr0], se0);
                atomicAdd(&rowsum[lr1], se1);
            }
        }
    }
}

// ---------------------------------------------------------------------------
// Generic batched GEMM kernel (QK, PV, O-proj)
// ---------------------------------------------------------------------------
__global__ void __launch_bounds__(NTHREADS, 2)
gemm_f16(const __half* __restrict__ A, const __half* __restrict__ B,
         __half* __restrict__ Hf, float* __restrict__ Cf,
         float* __restrict__ rowsum, int fuse,
         int K, int lda, int ldb, int ldc, float alpha,
         long long aSB, long long aSH, long long bSB, long long bSH,
         long long cSB, long long cSH, int H)
{
    extern __shared__ char smem[];
    const uint32_t sbase = smem_u32(smem);

    const int zb = blockIdx.z / H;
    const int zh = blockIdx.z - zb * H;
    const int rowBase = blockIdx.y * BM;
    const int colBase = blockIdx.x * BN;

    const __half* A_ = A + zb * aSB + zh * aSH + (long long)rowBase * lda;
    const __half* B_ = B + zb * bSB + zh * bSH + (long long)colBase * ldb;
    const long long cOff = zb * cSB + zh * cSH;

    gemm_body(A_, B_,
              Hf ? Hf + cOff : nullptr,
              Cf ? Cf + cOff : nullptr,
              rowsum + (long long)blockIdx.z * SEQ, fuse,
              K >> 6, lda, ldb, ldc, alpha, rowBase, colBase, sbase);
}

// ---------------------------------------------------------------------------
// Merged projection kernel: one launch covers QK-proj and V-proj.
//   bid <  640: QK-proj  QKbuf = Xf @ Wqk^T  (grid 10 x 64)
//   bid >= 640: V-proj   Vt[b] = Wv @ Xf[b]^T (2 batches x (32 x 2))
// ---------------------------------------------------------------------------
__global__ void __launch_bounds__(NTHREADS, 2)
proj_merged(const __half* __restrict__ Xf, const __half* __restrict__ Wqk,
            const __half* __restrict__ Wv, __half* __restrict__ QKb,
            __half* __restrict__ Vt)
{
    extern __shared__ char smem[];
    const uint32_t sbase = smem_u32(smem);
    const int bid = blockIdx.x;

    if (bid < 640) {
        const int x = bid % (DQK / BN);       // 0..9
        const int y = bid / (DQK / BN);       // 0..63
        const int rowBase = y * BM;
        const int colBase = x * BN;
        gemm_body(Xf + (long long)rowBase * DMODEL,
                  Wqk + (long long)colBase * DMODEL,
                  QKb, nullptr, nullptr, 0,
                  DMODEL >> 6, DMODEL, DMODEL, DQK, 1.0f,
                  rowBase, colBase, sbase);
    } else {
        const int t = bid - 640;
        const int zb = t / 64;                // batch
        const int rem = t - zb * 64;
        const int x = rem % (SEQ / BN);       // 0..31
        const int y = rem / (SEQ / BN);       // 0..1
        const int rowBase = y * BM;
        const int colBase = x * BN;
        gemm_body(Wv + (long long)rowBase * DMODEL,
                  Xf + (long long)zb * SEQ * DMODEL + (long long)colBase * DMODEL,
                  Vt + (long long)zb * DK * SEQ, nullptr, nullptr, 0,
                  DMODEL >> 6, DMODEL, DMODEL, SEQ, 1.0f,
                  rowBase, colBase, sbase);
    }
}

// ---------------------------------------------------------------------------
// Merged split kernel: all fp32->fp16 conversions + rowsum zeroing, 1 launch.
//   [0, 8192)        X  -> Xf
//   [8192, 9216)     Wq -> Wqk rows 0-1023
//   [9216, 9472)     Wk -> Wqk rows 1024-1279
//   [9472, 9728)     Wv -> Wvf
//   [9728, 10752)    Wo -> Wof
//   [10752, 10784)   zero g_rowsum
// ---------------------------------------------------------------------------
__global__ void __launch_bounds__(256)
split_all(const float* __restrict__ X,  const float* __restrict__ Wq,
          const float* __restrict__ Wk, const float* __restrict__ Wv,
          const float* __restrict__ Wo,
          __half* __restrict__ Xf, __half* __restrict__ Wqk,
          __half* __restrict__ Wvf, __half* __restrict__ Wof,
          float* __restrict__ rowsum)
{
    const int bid = blockIdx.x;
    const int tid = threadIdx.x;

    const float* src;
    __half* dst;
    long long i;

    if (bid < 8192) {
        src = X;  dst = Xf;  i = (long long)bid * 256 + tid;
    } else if (bid < 9216) {
        src = Wq; dst = Wqk; i = (long long)(bid - 8192) * 256 + tid;
    } else if (bid < 9472) {
        src = Wk; dst = Wqk + (size_t)DMODEL * DMODEL;
        i = (long long)(bid - 9216) * 256 + tid;
    } else if (bid < 9728) {
        src = Wv; dst = Wvf; i = (long long)(bid - 9472) * 256 + tid;
    } else if (bid < 10752) {
        src = Wo; dst = Wof; i = (long long)(bid - 9728) * 256 + tid;
    } else {
        long long z = (long long)(bid - 10752) * 256 + tid;
        reinterpret_cast<float4*>(rowsum)[z] = make_float4(0.f, 0.f, 0.f, 0.f);
        return;
    }

    float4 v = reinterpret_cast<const float4*>(src)[i];
    __half2 a, b;
    a.x = __float2half(v.x); a.y = __float2half(v.y);
    b.x = __float2half(v.z); b.y = __float2half(v.w);
    reinterpret_cast<__half2*>(dst)[2 * i] = a;
    reinterpret_cast<__half2*>(dst)[2 * i + 1] = b;
}

static void* sym_addr(const void* symbol)
{
    void* p = nullptr;
    cudaGetSymbolAddress(&p, symbol);
    return p;
}

extern "C" void kernel_launch(void* const* d_in, const int* in_sizes, int n_in,
                              void* d_out, int out_size)
{
    const float* X  = (const float*)d_in[0];
    const float* Wq = (const float*)d_in[1];
    const float* Wk = (const float*)d_in[2];
    const float* Wv = (const float*)d_in[3];
    const float* Wo = (const float*)d_in[4];
    float* out = (float*)d_out;

    __half* Xf  = (__half*)sym_addr(g_Xf);
    __half* Wqk = (__half*)sym_addr(g_Wqk);
    __half* Wvf = (__half*)sym_addr(g_Wv);
    __half* Wof = (__half*)sym_addr(g_Wo);
    __half* QKb = (__half*)sym_addr(g_QK);
    __half* Vt  = (__half*)sym_addr(g_Vt);
    __half* S   = (__half*)sym_addr(g_S);
    __half* M   = (__half*)sym_addr(g_M);
    float*  rs  = (float*)sym_addr(g_rowsum);

    cudaFuncSetAttribute(gemm_f16, cudaFuncAttributeMaxDynamicSharedMemorySize,
                         G1_SMEM);
    cudaFuncSetAttribute(proj_merged, cudaFuncAttributeMaxDynamicSharedMemorySize,
                         G1_SMEM);

    // 1 launch: all fp32->fp16 splits + rowsum zeroing
    split_all<<<10784, 256>>>(X, Wq, Wk, Wv, Wo, Xf, Wqk, Wvf, Wof, rs);

    // 1 launch: QK-proj (merged Q|K) + V-proj
    proj_merged<<<768, NTHREADS, G1_SMEM>>>(Xf, Wqk, Wvf, QKb, Vt);

    // S[b,h] = exp(SCALE * Q[b,h] @ K[b]^T) -> fp16, rowsum accumulated
    gemm_f16<<<dim3(SEQ / BN, SEQ / BM, BATCH * NHEAD), NTHREADS, G1_SMEM>>>(
        QKb, QKb + DMODEL, S, nullptr, rs, 1,
        DK, DQK, DQK, SEQ, SCALE_F,
        (long long)SEQ * DQK, DK,
        (long long)SEQ * DQK, 0,
        (long long)NHEAD * SEQ * SEQ, (long long)SEQ * SEQ, NHEAD);

    // M = (S @ VcT^T) / rowsum -> fp16 merged [8192 x 1024]
    gemm_f16<<<dim3(DK / BN, SEQ / BM, BATCH * NHEAD), NTHREADS, G1_SMEM>>>(
        S, Vt, M, nullptr, rs, 2,
        SEQ, SEQ, SEQ, DMODEL, 1.0f,
        (long long)NHEAD * SEQ * SEQ, (long long)SEQ * SEQ,
        (long long)DK * SEQ, 0,
        (long long)SEQ * DMODEL, DK, NHEAD);

    // out = M @ Wo^T -> fp32 (1-phase)
    gemm_f16<<<dim3(DMODEL / BN, MS / BM, 1), NTHREADS, G1_SMEM>>>(
        M, Wof, nullptr, out, rs, 3,
        DMODEL, DMODEL, DMODEL, DMODEL, 1.0f,
        0, 0, 0, 0, 0, 0, 1);
}

// round 15
// speedup vs baseline: 1.1424x; 1.0011x over previous
#include <cuda_runtime.h>
#include <cuda_fp16.h>
#include <cstdint>
#include <math.h>

#define BATCH 2
#define SEQ   4096
#define DMODEL 1024
#define NHEAD 4
#define DK    256
#define MS (BATCH * SEQ)
#define SCALE_F (1.0f / 16.0f)
#define DQK (DMODEL + DK)          // 1280: merged Q|K projection width

#define BM 128
#define BN 128
#define TILE_B 16384
#define NTHREADS 128               // 4 warps, 2x2 warp grid, 64x64 warp tile

// 1-phase GEMMs: 2 tiles/stage, 3 stages -> 96KB, 2 CTA/SM
#define STAGES 3
#define STAGE2_B (2 * TILE_B)
#define G1_SMEM (STAGES * STAGE2_B)

// ---------------------------------------------------------------------------
// Device scratch
// ---------------------------------------------------------------------------
__device__ __align__(256) __half g_Xf[(size_t)MS * DMODEL];
__device__ __align__(256) __half g_Wqk[(size_t)DQK * DMODEL];   // Wq rows 0-1023, Wk rows 1024-1279
__device__ __align__(256) __half g_Wv[(size_t)DK * DMODEL];
__device__ __align__(256) __half g_Wo[(size_t)DMODEL * DMODEL];
__device__ __align__(256) __half g_QK[(size_t)MS * DQK];        // Q cols 0-1023, K cols 1024-1279
__device__ __align__(256) __half g_Vt[(size_t)BATCH * DK * SEQ];
__device__ __align__(256) __half g_S[(size_t)BATCH * NHEAD * SEQ * SEQ];
__device__ __align__(256) __half g_M[(size_t)MS * DMODEL];
__device__ __align__(256) float  g_rowsum[(size_t)BATCH * NHEAD * SEQ];

// ---------------------------------------------------------------------------
// PTX helpers
// ---------------------------------------------------------------------------
__device__ __forceinline__ uint32_t smem_u32(const void* p) {
    uint32_t a;
    asm("{ .reg .u64 t; cvta.to.shared.u64 t, %1; cvt.u32.u64 %0, t; }"
        : "=r"(a) : "l"(p));
    return a;
}
__device__ __forceinline__ void cp16(uint32_t s, const void* g) {
    asm volatile("cp.async.cg.shared.global [%0], [%1], 16;" :: "r"(s), "l"(g));
}
#define CP_COMMIT() asm volatile("cp.async.commit_group;" ::: "memory")
#define CP_WAIT2()  asm volatile("cp.async.wait_group 2;" ::: "memory")

__device__ __forceinline__ void ldsm4(uint32_t* r, uint32_t addr) {
    asm volatile("ldmatrix.sync.aligned.m8n8.x4.shared.b16 {%0,%1,%2,%3}, [%4];"
                 : "=r"(r[0]), "=r"(r[1]), "=r"(r[2]), "=r"(r[3]) : "r"(addr));
}
__device__ __forceinline__ void mma_f16(float* c, const uint32_t* a,
                                        uint32_t b0, uint32_t b1) {
    asm volatile(
        "mma.sync.aligned.m16n8k16.row.col.f32.f16.f16.f32 "
        "{%0,%1,%2,%3}, {%4,%5,%6,%7}, {%8,%9}, {%0,%1,%2,%3};\n"
        : "+f"(c[0]), "+f"(c[1]), "+f"(c[2]), "+f"(c[3])
        : "r"(a[0]), "r"(a[1]), "r"(a[2]), "r"(a[3]), "r"(b0), "r"(b1));
}

// ---------------------------------------------------------------------------
// Shared GEMM body: 1-phase fp16, 128x128 CTA tile, 4 warps (64x64 warp tile),
// 3-stage cp.async pipeline. ldsm addresses strength-reduced:
//   row & 7 depends only on lane (rowBases are multiples of 16), so the
//   swizzle offset ((2ks|c0) ^ r7) << 4 is shared by ALL fragments at a given
//   ks; per-fragment row terms are loop-invariant. Each ldsm address is then
//   a single 3-input add. Bit-identical to the previous frag_addr.
// fuse 0: fp16 out. fuse 1: out = exp(alpha*acc) fp16 + rowsum atomics.
// fuse 2: out = acc / rowsum[row] fp16. fuse 3: fp32 out.
// ---------------------------------------------------------------------------
__device__ __forceinline__ void gemm_body(
    const __half* __restrict__ A_, const __half* __restrict__ B_,
    __half* __restrict__ Hf, float* __restrict__ Cf,
    float* __restrict__ rowsum, int fuse,
    int nK, int lda, int ldb, int ldc, float alpha,
    int rowBase, int colBase, uint32_t sbase)
{
    const int tid = threadIdx.x;
    const int wid = tid >> 5;          // 0..3
    const int lid = tid & 31;
    const int warpM = (wid >> 1) * 64; // 2x2 warp grid
    const int warpN = (wid & 1) * 64;

    // precomputed ldsm addressing (see header comment)
    const int c0 = lid >> 4;
    const int r7 = lid & 7;
    uint32_t swoff[4];
#pragma unroll
    for (int ks = 0; ks < 4; ks++)
        swoff[ks] = (uint32_t)(((((ks * 2) | c0) ^ r7) << 4));
    uint32_t rtA[4], rtB[4];
#pragma unroll
    for (int i = 0; i < 4; i++)
        rtA[i] = (uint32_t)((warpM + i * 16 + (lid & 15)) * 128);
#pragma unroll
    for (int jg = 0; jg < 4; jg++)
        rtB[jg] = (uint32_t)(TILE_B + (warpN + jg * 16 + (lid & 15)) * 128);

    float acc[4][8][4];
#pragma unroll
    for (int i = 0; i < 4; i++)
#pragma unroll
        for (int j = 0; j < 8; j++)
#pragma unroll
            for (int v = 0; v < 4; v++) acc[i][j][v] = 0.0f;

    auto load_stage = [&](int t, int buf) {
        const int k0 = t << 6;
        const uint32_t sS = sbase + buf * STAGE2_B;
        const __half* src[2] = {A_, B_};
        const int lds[2] = {lda, ldb};
#pragma unroll
        for (int tl = 0; tl < 2; tl++) {
            const __half* Q = src[tl];
            const int ld = lds[tl];
            const uint32_t tb = sS + tl * TILE_B;
#pragma unroll
            for (int j = 0; j < 8; j++) {
                int idx = tid + j * NTHREADS;   // 0..1023
                int row = idx >> 3;
                int c = idx & 7;
                int sw = c ^ (row & 7);
                cp16(tb + row * 128 + sw * 16,
                     Q + (long long)row * ld + k0 + c * 8);
            }
        }
    };

#pragma unroll
    for (int s = 0; s < STAGES; s++) {
        if (s < nK) load_stage(s, s);
        CP_COMMIT();
    }

    for (int t = 0; t < nK; t++) {
        const int buf = t % STAGES;
        CP_WAIT2();
        __syncthreads();

        const uint32_t sS = sbase + buf * STAGE2_B;

#pragma unroll
        for (int ks = 0; ks < 4; ks++) {
            uint32_t a[4][4], b[4][4];
#pragma unroll
            for (int i = 0; i < 4; i++)
                ldsm4(a[i], sS + rtA[i] + swoff[ks]);
#pragma unroll
            for (int jg = 0; jg < 4; jg++)
                ldsm4(b[jg], sS + rtB[jg] + swoff[ks]);

#pragma unroll
            for (int i = 0; i < 4; i++) {
#pragma unroll
                for (int j = 0; j < 8; j++) {
                    mma_f16(acc[i][j], a[i],
                            b[j >> 1][j & 1], b[j >> 1][(j & 1) + 2]);
                }
            }
        }
        __syncthreads();

        const int nt = t + STAGES;
        if (nt < nK) load_stage(nt, buf);
        CP_COMMIT();
    }

    const int g = lid >> 2;
    const int tq = lid & 3;

#pragma unroll
    for (int i = 0; i < 4; i++) {
        const int lr0 = rowBase + warpM + i * 16 + g;
        const int lr1 = lr0 + 8;
        const long long r0 = lr0, r1 = lr1;

        float inv0 = 1.0f, inv1 = 1.0f;
        if (fuse == 2) {
            inv0 = __frcp_rn(rowsum[lr0]);
            inv1 = __frcp_rn(rowsum[lr1]);
        }
        float se0 = 0.0f, se1 = 0.0f;

#pragma unroll
        for (int j = 0; j < 8; j++) {
            const int col = colBase + warpN + j * 8 + tq * 2;
            float x0 = acc[i][j][0] * alpha, x1 = acc[i][j][1] * alpha;
            float x2 = acc[i][j][2] * alpha, x3 = acc[i][j][3] * alpha;
            if (fuse == 1) {
                x0 = __expf(x0); x1 = __expf(x1);
                x2 = __expf(x2); x3 = __expf(x3);
                se0 += x0 + x1;
                se1 += x2 + x3;
            } else if (fuse == 2) {
                x0 *= inv0; x1 *= inv0;
                x2 *= inv1; x3 *= inv1;
            }
            if (fuse == 3) {
                *reinterpret_cast<float2*>(Cf + r0 * ldc + col) =
                    make_float2(x0, x1);
                *reinterpret_cast<float2*>(Cf + r1 * ldc + col) =
                    make_float2(x2, x3);
            } else {
                *reinterpret_cast<__half2*>(Hf + r0 * ldc + col) =
                    __floats2half2_rn(x0, x1);
                *reinterpret_cast<__half2*>(Hf + r1 * ldc + col) =
                    __floats2half2_rn(x2, x3);
            }
        }

        if (fuse == 1) {
            se0 += __shfl_xor_sync(0xffffffffu, se0, 1);
            se0 += __shfl_xor_sync(0xffffffffu, se0, 2);
            se1 += __shfl_xor_sync(0xffffffffu, se1, 1);
            se1 += __shfl_xor_sync(0xffffffffu, se1, 2);
            if (tq == 0) {
                atomicAdd(&rowsum[lr0], se0);
                atomicAdd(&rowsum[lr1], se1);
            }
        }
    }
}

// ---------------------------------------------------------------------------
// Generic batched GEMM kernel (QK, PV, O-proj)
// ---------------------------------------------------------------------------
__global__ void __launch_bounds__(NTHREADS, 2)
gemm_f16(const __half* __restrict__ A, const __half* __restrict__ B,
         __half* __restrict__ Hf, float* __restrict__ Cf,
         float* __restrict__ rowsum, int fuse,
         int K, int lda, int ldb, int ldc, float alpha,
         long long aSB, long long aSH, long long bSB, long long bSH,
         long long cSB, long long cSH, int H)
{
    extern __shared__ char smem[];
    const uint32_t sbase = smem_u32(smem);

    const int zb = blockIdx.z / H;
    const int zh = blockIdx.z - zb * H;
    const int rowBase = blockIdx.y * BM;
    const int colBase = blockIdx.x * BN;

    const __half* A_ = A + zb * aSB + zh * aSH + (long long)rowBase * lda;
    const __half* B_ = B + zb * bSB + zh * bSH + (long long)colBase * ldb;
    const long long cOff = zb * cSB + zh * cSH;

    gemm_body(A_, B_,
              Hf ? Hf + cOff : nullptr,
              Cf ? Cf + cOff : nullptr,
              rowsum + (long long)blockIdx.z * SEQ, fuse,
              K >> 6, lda, ldb, ldc, alpha, rowBase, colBase, sbase);
}

// ---------------------------------------------------------------------------
// Merged projection kernel: one launch covers QK-proj and V-proj.
//   bid <  640: QK-proj  QKbuf = Xf @ Wqk^T  (grid 10 x 64)
//   bid >= 640: V-proj   Vt[b] = Wv @ Xf[b]^T (2 batches x (32 x 2))
// ---------------------------------------------------------------------------
__global__ void __launch_bounds__(NTHREADS, 2)
proj_merged(const __half* __restrict__ Xf, const __half* __restrict__ Wqk,
            const __half* __restrict__ Wv, __half* __restrict__ QKb,
            __half* __restrict__ Vt)
{
    extern __shared__ char smem[];
    const uint32_t sbase = smem_u32(smem);
    const int bid = blockIdx.x;

    if (bid < 640) {
        const int x = bid % (DQK / BN);       // 0..9
        const int y = bid / (DQK / BN);       // 0..63
        const int rowBase = y * BM;
        const int colBase = x * BN;
        gemm_body(Xf + (long long)rowBase * DMODEL,
                  Wqk + (long long)colBase * DMODEL,
                  QKb, nullptr, nullptr, 0,
                  DMODEL >> 6, DMODEL, DMODEL, DQK, 1.0f,
                  rowBase, colBase, sbase);
    } else {
        const int t = bid - 640;
        const int zb = t / 64;                // batch
        const int rem = t - zb * 64;
        const int x = rem % (SEQ / BN);       // 0..31
        const int y = rem / (SEQ / BN);       // 0..1
        const int rowBase = y * BM;
        const int colBase = x * BN;
        gemm_body(Wv + (long long)rowBase * DMODEL,
                  Xf + (long long)zb * SEQ * DMODEL + (long long)colBase * DMODEL,
                  Vt + (long long)zb * DK * SEQ, nullptr, nullptr, 0,
                  DMODEL >> 6, DMODEL, DMODEL, SEQ, 1.0f,
                  rowBase, colBase, sbase);
    }
}

// ---------------------------------------------------------------------------
// Merged split kernel: all fp32->fp16 conversions + rowsum zeroing, 1 launch.
//   [0, 8192)        X  -> Xf
//   [8192, 9216)     Wq -> Wqk rows 0-1023
//   [9216, 9472)     Wk -> Wqk rows 1024-1279
//   [9472, 9728)     Wv -> Wvf
//   [9728, 10752)    Wo -> Wof
//   [10752, 10784)   zero g_rowsum
// ---------------------------------------------------------------------------
__global__ void __launch_bounds__(256)
split_all(const float* __restrict__ X,  const float* __restrict__ Wq,
          const float* __restrict__ Wk, const float* __restrict__ Wv,
          const float* __restrict__ Wo,
          __half* __restrict__ Xf, __half* __restrict__ Wqk,
          __half* __restrict__ Wvf, __half* __restrict__ Wof,
          float* __restrict__ rowsum)
{
    const int bid = blockIdx.x;
    const int tid = threadIdx.x;

    const float* src;
    __half* dst;
    long long i;

    if (bid < 8192) {
        src = X;  dst = Xf;  i = (long long)bid * 256 + tid;
    } else if (bid < 9216) {
        src = Wq; dst = Wqk; i = (long long)(bid - 8192) * 256 + tid;
    } else if (bid < 9472) {
        src = Wk; dst = Wqk + (size_t)DMODEL * DMODEL;
        i = (long long)(bid - 9216) * 256 + tid;
    } else if (bid < 9728) {
        src = Wv; dst = Wvf; i = (long long)(bid - 9472) * 256 + tid;
    } else if (bid < 10752) {
        src = Wo; dst = Wof; i = (long long)(bid - 9728) * 256 + tid;
    } else {
        long long z = (long long)(bid - 10752) * 256 + tid;
        reinterpret_cast<float4*>(rowsum)[z] = make_float4(0.f, 0.f, 0.f, 0.f);
        return;
    }

    float4 v = reinterpret_cast<const float4*>(src)[i];
    __half2 a, b;
    a.x = __float2half(v.x); a.y = __float2half(v.y);
    b.x = __float2half(v.z); b.y = __float2half(v.w);
    reinterpret_cast<__half2*>(dst)[2 * i] = a;
    reinterpret_cast<__half2*>(dst)[2 * i + 1] = b;
}

static void* sym_addr(const void* symbol)
{
    void* p = nullptr;
    cudaGetSymbolAddress(&p, symbol);
    return p;
}

extern "C" void kernel_launch(void* const* d_in, const int* in_sizes, int n_in,
                              void* d_out, int out_size)
{
    const float* X  = (const float*)d_in[0];
    const float* Wq = (const float*)d_in[1];
    const float* Wk = (const float*)d_in[2];
    const float* Wv = (const float*)d_in[3];
    const float* Wo = (const float*)d_in[4];
    float* out = (float*)d_out;

    __half* Xf  = (__half*)sym_addr(g_Xf);
    __half* Wqk = (__half*)sym_addr(g_Wqk);
    __half* Wvf = (__half*)sym_addr(g_Wv);
    __half* Wof = (__half*)sym_addr(g_Wo);
    __half* QKb = (__half*)sym_addr(g_QK);
    __half* Vt  = (__half*)sym_addr(g_Vt);
    __half* S   = (__half*)sym_addr(g_S);
    __half* M   = (__half*)sym_addr(g_M);
    float*  rs  = (float*)sym_addr(g_rowsum);

    cudaFuncSetAttribute(gemm_f16, cudaFuncAttributeMaxDynamicSharedMemorySize,
                         G1_SMEM);
    cudaFuncSetAttribute(proj_merged, cudaFuncAttributeMaxDynamicSharedMemorySize,
                         G1_SMEM);

    // 1 launch: all fp32->fp16 splits + rowsum zeroing
    split_all<<<10784, 256>>>(X, Wq, Wk, Wv, Wo, Xf, Wqk, Wvf, Wof, rs);

    // 1 launch: QK-proj (merged Q|K) + V-proj
    proj_merged<<<768, NTHREADS, G1_SMEM>>>(Xf, Wqk, Wvf, QKb, Vt);

    // S[b,h] = exp(SCALE * Q[b,h] @ K[b]^T) -> fp16, rowsum accumulated
    gemm_f16<<<dim3(SEQ / BN, SEQ / BM, BATCH * NHEAD), NTHREADS, G1_SMEM>>>(
        QKb, QKb + DMODEL, S, nullptr, rs, 1,
        DK, DQK, DQK, SEQ, SCALE_F,
        (long long)SEQ * DQK, DK,
        (long long)SEQ * DQK, 0,
        (long long)NHEAD * SEQ * SEQ, (long long)SEQ * SEQ, NHEAD);

    // M = (S @ VcT^T) / rowsum -> fp16 merged [8192 x 1024]
    gemm_f16<<<dim3(DK / BN, SEQ / BM, BATCH * NHEAD), NTHREADS, G1_SMEM>>>(
        S, Vt, M, nullptr, rs, 2,
        SEQ, SEQ, SEQ, DMODEL, 1.0f,
        (long long)NHEAD * SEQ * SEQ, (long long)SEQ * SEQ,
        (long long)DK * SEQ, 0,
        (long long)SEQ * DMODEL, DK, NHEAD);

    // out = M @ Wo^T -> fp32 (1-phase)
    gemm_f16<<<dim3(DMODEL / BN, MS / BM, 1), NTHREADS, G1_SMEM>>>(
        M, Wof, nullptr, out, rs, 3,
        DMODEL, DMODEL, DMODEL, DMODEL, 1.0f,
        0, 0, 0, 0, 0, 0, 1);
}

// round 16
// speedup vs baseline: 1.1939x; 1.0451x over previous
#include <cuda_runtime.h>
#include <cuda_fp16.h>
#include <cstdint>
#include <math.h>

#define BATCH 2
#define SEQ   4096
#define DMODEL 1024
#define NHEAD 4
#define DK    256
#define MS (BATCH * SEQ)
#define SCALE_F (1.0f / 16.0f)
#define DQK (DMODEL + DK)          // 1280: merged Q|K projection width

#define BM 128
#define BN 128
#define TILE_B 16384
#define NTHREADS 128               // 4 warps, 2x2 warp grid, 64x64 warp tile

// 1-phase GEMMs: 2 tiles/stage, 3 stages -> 96KB, 2 CTA/SM
#define STAGES 3
#define STAGE2_B (2 * TILE_B)
#define G1_SMEM (STAGES * STAGE2_B)

// ---------------------------------------------------------------------------
// Device scratch
// ---------------------------------------------------------------------------
__device__ __align__(256) __half g_Xf[(size_t)MS * DMODEL];
__device__ __align__(256) __half g_Wqk[(size_t)DQK * DMODEL];   // Wq rows 0-1023, Wk rows 1024-1279
__device__ __align__(256) __half g_Wv[(size_t)DK * DMODEL];
__device__ __align__(256) __half g_Wo[(size_t)DMODEL * DMODEL];
__device__ __align__(256) __half g_QK[(size_t)MS * DQK];        // Q cols 0-1023, K cols 1024-1279
__device__ __align__(256) __half g_Vt[(size_t)BATCH * DK * SEQ];
__device__ __align__(256) __half g_S[(size_t)BATCH * NHEAD * SEQ * SEQ];
__device__ __align__(256) __half g_M[(size_t)MS * DMODEL];
__device__ __align__(256) float  g_rowsum[(size_t)BATCH * NHEAD * SEQ];

// ---------------------------------------------------------------------------
// PTX helpers
// ---------------------------------------------------------------------------
__device__ __forceinline__ uint32_t smem_u32(const void* p) {
    uint32_t a;
    asm("{ .reg .u64 t; cvta.to.shared.u64 t, %1; cvt.u32.u64 %0, t; }"
        : "=r"(a) : "l"(p));
    return a;
}
__device__ __forceinline__ void cp16(uint32_t s, const void* g) {
    asm volatile("cp.async.cg.shared.global [%0], [%1], 16;" :: "r"(s), "l"(g));
}
#define CP_COMMIT() asm volatile("cp.async.commit_group;" ::: "memory")
#define CP_WAIT2()  asm volatile("cp.async.wait_group 2;" ::: "memory")

__device__ __forceinline__ void ldsm4(uint32_t* r, uint32_t addr) {
    asm volatile("ldmatrix.sync.aligned.m8n8.x4.shared.b16 {%0,%1,%2,%3}, [%4];"
                 : "=r"(r[0]), "=r"(r[1]), "=r"(r[2]), "=r"(r[3]) : "r"(addr));
}
__device__ __forceinline__ void mma_f16(float* c, const uint32_t* a,
                                        uint32_t b0, uint32_t b1) {
    asm volatile(
        "mma.sync.aligned.m16n8k16.row.col.f32.f16.f16.f32 "
        "{%0,%1,%2,%3}, {%4,%5,%6,%7}, {%8,%9}, {%0,%1,%2,%3};\n"
        : "+f"(c[0]), "+f"(c[1]), "+f"(c[2]), "+f"(c[3])
        : "r"(a[0]), "r"(a[1]), "r"(a[2]), "r"(a[3]), "r"(b0), "r"(b1));
}

// ---------------------------------------------------------------------------
// Shared GEMM body, templated on leading dimensions (all call sites are
// compile-time). Load addressing uses two exact identities:
//   row = (tid>>3) + j*16, and the xor-swizzle term is j-independent
//   (j*16 = 0 mod 8), so smem offset = so + j*2048 with so thread-constant;
//   global offset = gX + t*64 + j*16*LD with the j term an immediate.
// Bit-identical addresses to the previous version; ~8x less address ALU.
// fuse 0: fp16 out. fuse 1: out = exp(alpha*acc) fp16 + rowsum atomics.
// fuse 2: out = acc / rowsum[row] fp16. fuse 3: fp32 out.
// ---------------------------------------------------------------------------
template <int LDA, int LDB>
__device__ __forceinline__ void gemm_body(
    const __half* __restrict__ A_, const __half* __restrict__ B_,
    __half* __restrict__ Hf, float* __restrict__ Cf,
    float* __restrict__ rowsum, int fuse,
    int nK, int ldc, float alpha,
    int rowBase, int colBase, uint32_t sbase)
{
    const int tid = threadIdx.x;
    const int wid = tid >> 5;          // 0..3
    const int lid = tid & 31;
    const int warpM = (wid >> 1) * 64; // 2x2 warp grid
    const int warpN = (wid & 1) * 64;

    // ldsm addressing (swizzle invariant across fragments at fixed ks)
    const int c0 = lid >> 4;
    const int r7 = lid & 7;
    uint32_t swoff[4];
#pragma unroll
    for (int ks = 0; ks < 4; ks++)
        swoff[ks] = (uint32_t)(((((ks * 2) | c0) ^ r7) << 4));
    uint32_t rtA[4], rtB[4];
#pragma unroll
    for (int i = 0; i < 4; i++)
        rtA[i] = (uint32_t)((warpM + i * 16 + (lid & 15)) * 128);
#pragma unroll
    for (int jg = 0; jg < 4; jg++)
        rtB[jg] = (uint32_t)(TILE_B + (warpN + jg * 16 + (lid & 15)) * 128);

    // cp.async addressing: thread-constant smem offset + immediate j terms
    const int lrow = tid >> 3;                       // 0..15
    const int cc = tid & 7;
    const uint32_t so = (uint32_t)(lrow * 128 + ((cc ^ (lrow & 7)) << 4));
    const __half* gA = A_ + (long long)lrow * LDA + cc * 8;
    const __half* gB = B_ + (long long)lrow * LDB + cc * 8;

    float acc[4][8][4];
#pragma unroll
    for (int i = 0; i < 4; i++)
#pragma unroll
        for (int j = 0; j < 8; j++)
#pragma unroll
            for (int v = 0; v < 4; v++) acc[i][j][v] = 0.0f;

    auto load_stage = [&](int t, int buf) {
        const __half* pA = gA + (long long)t * 64;
        const __half* pB = gB + (long long)t * 64;
        const uint32_t tbA = sbase + buf * STAGE2_B + so;
        const uint32_t tbB = tbA + TILE_B;
#pragma unroll
        for (int j = 0; j < 8; j++)
            cp16(tbA + j * 2048, pA + (long long)j * 16 * LDA);
#pragma unroll
        for (int j = 0; j < 8; j++)
            cp16(tbB + j * 2048, pB + (long long)j * 16 * LDB);
    };

#pragma unroll
    for (int s = 0; s < STAGES; s++) {
        if (s < nK) load_stage(s, s);
        CP_COMMIT();
    }

    for (int t = 0; t < nK; t++) {
        const int buf = t % STAGES;
        CP_WAIT2();
        __syncthreads();

        const uint32_t sS = sbase + buf * STAGE2_B;

#pragma unroll
        for (int ks = 0; ks < 4; ks++) {
            uint32_t a[4][4], b[4][4];
#pragma unroll
            for (int i = 0; i < 4; i++)
                ldsm4(a[i], sS + rtA[i] + swoff[ks]);
#pragma unroll
            for (int jg = 0; jg < 4; jg++)
                ldsm4(b[jg], sS + rtB[jg] + swoff[ks]);

#pragma unroll
            for (int i = 0; i < 4; i++) {
#pragma unroll
                for (int j = 0; j < 8; j++) {
                    mma_f16(acc[i][j], a[i],
                            b[j >> 1][j & 1], b[j >> 1][(j & 1) + 2]);
                }
            }
        }
        __syncthreads();

        const int nt = t + STAGES;
        if (nt < nK) load_stage(nt, buf);
        CP_COMMIT();
    }

    const int g = lid >> 2;
    const int tq = lid & 3;

#pragma unroll
    for (int i = 0; i < 4; i++) {
        const int lr0 = rowBase + warpM + i * 16 + g;
        const int lr1 = lr0 + 8;
        const long long r0 = lr0, r1 = lr1;

        float inv0 = 1.0f, inv1 = 1.0f;
        if (fuse == 2) {
            inv0 = __frcp_rn(rowsum[lr0]);
            inv1 = __frcp_rn(rowsum[lr1]);
        }
        float se0 = 0.0f, se1 = 0.0f;

#pragma unroll
        for (int j = 0; j < 8; j++) {
            const int col = colBase + warpN + j * 8 + tq * 2;
            float x0 = acc[i][j][0] * alpha, x1 = acc[i][j][1] * alpha;
            float x2 = acc[i][j][2] * alpha, x3 = acc[i][j][3] * alpha;
            if (fuse == 1) {
                x0 = __expf(x0); x1 = __expf(x1);
                x2 = __expf(x2); x3 = __expf(x3);
                se0 += x0 + x1;
                se1 += x2 + x3;
            } else if (fuse == 2) {
                x0 *= inv0; x1 *= inv0;
                x2 *= inv1; x3 *= inv1;
            }
            if (fuse == 3) {
                *reinterpret_cast<float2*>(Cf + r0 * ldc + col) =
                    make_float2(x0, x1);
                *reinterpret_cast<float2*>(Cf + r1 * ldc + col) =
                    make_float2(x2, x3);
            } else {
                *reinterpret_cast<__half2*>(Hf + r0 * ldc + col) =
                    __floats2half2_rn(x0, x1);
                *reinterpret_cast<__half2*>(Hf + r1 * ldc + col) =
                    __floats2half2_rn(x2, x3);
            }
        }

        if (fuse == 1) {
            se0 += __shfl_xor_sync(0xffffffffu, se0, 1);
            se0 += __shfl_xor_sync(0xffffffffu, se0, 2);
            se1 += __shfl_xor_sync(0xffffffffu, se1, 1);
            se1 += __shfl_xor_sync(0xffffffffu, se1, 2);
            if (tq == 0) {
                atomicAdd(&rowsum[lr0], se0);
                atomicAdd(&rowsum[lr1], se1);
            }
        }
    }
}

// ---------------------------------------------------------------------------
// Generic batched GEMM kernel (QK, PV, O-proj), templated on lds.
// ---------------------------------------------------------------------------
template <int LDA, int LDB>
__global__ void __launch_bounds__(NTHREADS, 2)
gemm_f16(const __half* __restrict__ A, const __half* __restrict__ B,
         __half* __restrict__ Hf, float* __restrict__ Cf,
         float* __restrict__ rowsum, int fuse,
         int K, int ldc, float alpha,
         long long aSB, long long aSH, long long bSB, long long bSH,
         long long cSB, long long cSH, int H)
{
    extern __shared__ char smem[];
    const uint32_t sbase = smem_u32(smem);

    const int zb = blockIdx.z / H;
    const int zh = blockIdx.z - zb * H;
    const int rowBase = blockIdx.y * BM;
    const int colBase = blockIdx.x * BN;

    const __half* A_ = A + zb * aSB + zh * aSH + (long long)rowBase * LDA;
    const __half* B_ = B + zb * bSB + zh * bSH + (long long)colBase * LDB;
    const long long cOff = zb * cSB + zh * cSH;

    gemm_body<LDA, LDB>(A_, B_,
                        Hf ? Hf + cOff : nullptr,
                        Cf ? Cf + cOff : nullptr,
                        rowsum + (long long)blockIdx.z * SEQ, fuse,
                        K >> 6, ldc, alpha, rowBase, colBase, sbase);
}

// ---------------------------------------------------------------------------
// Merged projection kernel: one launch covers QK-proj and V-proj
// (all operands have ld = DMODEL).
//   bid <  640: QK-proj  QKbuf = Xf @ Wqk^T  (grid 10 x 64)
//   bid >= 640: V-proj   Vt[b] = Wv @ Xf[b]^T (2 batches x (32 x 2))
// ---------------------------------------------------------------------------
__global__ void __launch_bounds__(NTHREADS, 2)
proj_merged(const __half* __restrict__ Xf, const __half* __restrict__ Wqk,
            const __half* __restrict__ Wv, __half* __restrict__ QKb,
            __half* __restrict__ Vt)
{
    extern __shared__ char smem[];
    const uint32_t sbase = smem_u32(smem);
    const int bid = blockIdx.x;

    if (bid < 640) {
        const int x = bid % (DQK / BN);       // 0..9
        const int y = bid / (DQK / BN);       // 0..63
        const int rowBase = y * BM;
        const int colBase = x * BN;
        gemm_body<DMODEL, DMODEL>(
            Xf + (long long)rowBase * DMODEL,
            Wqk + (long long)colBase * DMODEL,
            QKb, nullptr, nullptr, 0,
            DMODEL >> 6, DQK, 1.0f, rowBase, colBase, sbase);
    } else {
        const int t = bid - 640;
        const int zb = t / 64;                // batch
        const int rem = t - zb * 64;
        const int x = rem % (SEQ / BN);       // 0..31
        const int y = rem / (SEQ / BN);       // 0..1
        const int rowBase = y * BM;
        const int colBase = x * BN;
        gemm_body<DMODEL, DMODEL>(
            Wv + (long long)rowBase * DMODEL,
            Xf + (long long)zb * SEQ * DMODEL + (long long)colBase * DMODEL,
            Vt + (long long)zb * DK * SEQ, nullptr, nullptr, 0,
            DMODEL >> 6, SEQ, 1.0f, rowBase, colBase, sbase);
    }
}

// ---------------------------------------------------------------------------
// Merged split kernel: all fp32->fp16 conversions + rowsum zeroing, 1 launch.
//   [0, 8192)        X  -> Xf
//   [8192, 9216)     Wq -> Wqk rows 0-1023
//   [9216, 9472)     Wk -> Wqk rows 1024-1279
//   [9472, 9728)     Wv -> Wvf
//   [9728, 10752)    Wo -> Wof
//   [10752, 10784)   zero g_rowsum
// ---------------------------------------------------------------------------
__global__ void __launch_bounds__(256)
split_all(const float* __restrict__ X,  const float* __restrict__ Wq,
          const float* __restrict__ Wk, const float* __restrict__ Wv,
          const float* __restrict__ Wo,
          __half* __restrict__ Xf, __half* __restrict__ Wqk,
          __half* __restrict__ Wvf, __half* __restrict__ Wof,
          float* __restrict__ rowsum)
{
    const int bid = blockIdx.x;
    const int tid = threadIdx.x;

    const float* src;
    __half* dst;
    long long i;

    if (bid < 8192) {
        src = X;  dst = Xf;  i = (long long)bid * 256 + tid;
    } else if (bid < 9216) {
        src = Wq; dst = Wqk; i = (long long)(bid - 8192) * 256 + tid;
    } else if (bid < 9472) {
        src = Wk; dst = Wqk + (size_t)DMODEL * DMODEL;
        i = (long long)(bid - 9216) * 256 + tid;
    } else if (bid < 9728) {
        src = Wv; dst = Wvf; i = (long long)(bid - 9472) * 256 + tid;
    } else if (bid < 10752) {
        src = Wo; dst = Wof; i = (long long)(bid - 9728) * 256 + tid;
    } else {
        long long z = (long long)(bid - 10752) * 256 + tid;
        reinterpret_cast<float4*>(rowsum)[z] = make_float4(0.f, 0.f, 0.f, 0.f);
        return;
    }

    float4 v = reinterpret_cast<const float4*>(src)[i];
    __half2 a, b;
    a.x = __float2half(v.x); a.y = __float2half(v.y);
    b.x = __float2half(v.z); b.y = __float2half(v.w);
    reinterpret_cast<__half2*>(dst)[2 * i] = a;
    reinterpret_cast<__half2*>(dst)[2 * i + 1] = b;
}

static void* sym_addr(const void* symbol)
{
    void* p = nullptr;
    cudaGetSymbolAddress(&p, symbol);
    return p;
}

extern "C" void kernel_launch(void* const* d_in, const int* in_sizes, int n_in,
                              void* d_out, int out_size)
{
    const float* X  = (const float*)d_in[0];
    const float* Wq = (const float*)d_in[1];
    const float* Wk = (const float*)d_in[2];
    const float* Wv = (const float*)d_in[3];
    const float* Wo = (const float*)d_in[4];
    float* out = (float*)d_out;

    __half* Xf  = (__half*)sym_addr(g_Xf);
    __half* Wqk = (__half*)sym_addr(g_Wqk);
    __half* Wvf = (__half*)sym_addr(g_Wv);
    __half* Wof = (__half*)sym_addr(g_Wo);
    __half* QKb = (__half*)sym_addr(g_QK);
    __half* Vt  = (__half*)sym_addr(g_Vt);
    __half* S   = (__half*)sym_addr(g_S);
    __half* M   = (__half*)sym_addr(g_M);
    float*  rs  = (float*)sym_addr(g_rowsum);

    cudaFuncSetAttribute(gemm_f16<DQK, DQK>,
                         cudaFuncAttributeMaxDynamicSharedMemorySize, G1_SMEM);
    cudaFuncSetAttribute(gemm_f16<SEQ, SEQ>,
                         cudaFuncAttributeMaxDynamicSharedMemorySize, G1_SMEM);
    cudaFuncSetAttribute(gemm_f16<DMODEL, DMODEL>,
                         cudaFuncAttributeMaxDynamicSharedMemorySize, G1_SMEM);
    cudaFuncSetAttribute(proj_merged,
                         cudaFuncAttributeMaxDynamicSharedMemorySize, G1_SMEM);

    // 1 launch: all fp32->fp16 splits + rowsum zeroing
    split_all<<<10784, 256>>>(X, Wq, Wk, Wv, Wo, Xf, Wqk, Wvf, Wof, rs);

    // 1 launch: QK-proj (merged Q|K) + V-proj
    proj_merged<<<768, NTHREADS, G1_SMEM>>>(Xf, Wqk, Wvf, QKb, Vt);

    // S[b,h] = exp(SCALE * Q[b,h] @ K[b]^T) -> fp16, rowsum accumulated
    gemm_f16<DQK, DQK><<<dim3(SEQ / BN, SEQ / BM, BATCH * NHEAD), NTHREADS,
                         G1_SMEM>>>(
        QKb, QKb + DMODEL, S, nullptr, rs, 1,
        DK, SEQ, SCALE_F,
        (long long)SEQ * DQK, DK,
        (long long)SEQ * DQK, 0,
        (long long)NHEAD * SEQ * SEQ, (long long)SEQ * SEQ, NHEAD);

    // M = (S @ VcT^T) / rowsum -> fp16 merged [8192 x 1024]
    gemm_f16<SEQ, SEQ><<<dim3(DK / BN, SEQ / BM, BATCH * NHEAD), NTHREADS,
                         G1_SMEM>>>(
        S, Vt, M, nullptr, rs, 2,
        SEQ, DMODEL, 1.0f,
        (long long)NHEAD * SEQ * SEQ, (long long)SEQ * SEQ,
        (long long)DK * SEQ, 0,
        (long long)SEQ * DMODEL, DK, NHEAD);

    // out = M @ Wo^T -> fp32 (1-phase)
    gemm_f16<DMODEL, DMODEL><<<dim3(DMODEL / BN, MS / BM, 1), NTHREADS,
                               G1_SMEM>>>(
        M, Wof, nullptr, out, rs, 3,
        DMODEL, DMODEL, 1.0f,
        0, 0, 0, 0, 0, 0, 1);
}